// round 14
// baseline (speedup 1.0000x reference)
#include <cuda_runtime.h>
#include <math.h>

// Problem dims
#define NB 2
#define NC 16
#define NAM 4
#define NHEADS 8
#define NF 1024
#define NW 1024
#define NHD 128

// Tiled-slab layout: slab = 128 rows x 32 k, rows padded to 36 words -> 18432B contiguous
#define TSTR 36
#define TSLAB 4608
#define TSLAB_B 18432u
#define TMB 147456
#define TMAT 1179648

// ---------------- scratch (device globals; no runtime allocation) ----------------
__device__ float g_yt[3][8][TMAT];      // conv outputs tiled: rows=w, k=h
__device__ float g_qkm[2][8][TMAT];     // q,k tiled: rows=w, k=f
__device__ float g_vt[8][TMAT];         // V^T tiled: rows=f, k=w
__device__ float g_wt[4][4][TMAT];      // repacked weights [q,k,v,o][am]: rows=f, k=h
__device__ float g_aot[8][TMAT];        // after dw mix tiled: rows=w, k=h
__device__ float g_a[8][NW * NF];       // attention out plain [w][f]
__device__ float g_a2[8][NF * NW];      // after wo_pw plain [f][w]
__device__ float g_cos[NW * (NHD / 2)];
__device__ float g_sin[NW * (NHD / 2)];

// ---------------- helpers ----------------
__device__ __forceinline__ unsigned sptr(const void* p) {
    return (unsigned)__cvta_generic_to_shared(p);
}
__device__ __forceinline__ size_t tiled_off(int row, int k) {
    return (size_t)(row >> 7) * TMB + (size_t)(k >> 5) * TSLAB + (row & 127) * TSTR + (k & 31);
}

#define MBARRIER_INIT(addr, count) \
    asm volatile("mbarrier.init.shared.b64 [%0], %1;" ::"r"(addr), "r"(count) : "memory")

#define MBARRIER_WAIT_PARITY(addr, parity)                                              \
    do {                                                                                \
        unsigned _mb = (addr), _pa = (parity), _done;                                   \
        asm volatile(                                                                   \
            "{\n\t.reg .pred p;\n\t"                                                    \
            "mbarrier.try_wait.parity.acquire.cta.shared::cta.b64 p, [%1], %2;\n\t"     \
            "selp.b32 %0, 1, 0, p;\n\t}"                                                \
            : "=r"(_done) : "r"(_mb), "r"(_pa) : "memory");                             \
        if (!_done) {                                                                   \
            asm volatile(                                                               \
                "{\n\t.reg .pred P1;\n\t"                                               \
                "WL_%=:\n\t"                                                            \
                "mbarrier.try_wait.parity.acquire.cta.shared::cta.b64 P1, [%0], %1, 0x989680;\n\t" \
                "@P1 bra.uni WD_%=;\n\t"                                                \
                "bra.uni WL_%=;\n\t"                                                    \
                "WD_%=:\n\t}" ::"r"(_mb), "r"(_pa) : "memory");                         \
        }                                                                               \
    } while (0)

#define MBARRIER_ARRIVE(addr) \
    asm volatile("mbarrier.arrive.shared.b64 _, [%0];" ::"r"(addr) : "memory")

__device__ __forceinline__ void bulk_expect(unsigned mb, unsigned bytes) {
    asm volatile("mbarrier.arrive.expect_tx.shared.b64 _, [%0], %1;" ::"r"(mb), "r"(bytes)
                 : "memory");
}
__device__ __forceinline__ void bulk_cp_n(unsigned dst, const float* src, unsigned bytes,
                                          unsigned mb) {
    asm volatile(
        "cp.async.bulk.shared::cta.global.mbarrier::complete_tx::bytes [%0], [%1], %2, [%3];"
        ::"r"(dst), "l"(src), "r"(bytes), "r"(mb)
        : "memory");
}
__device__ __forceinline__ void bulk_cp(unsigned dst, const float* src, unsigned mb) {
    bulk_cp_n(dst, src, TSLAB_B, mb);
}

__device__ __forceinline__ void ldsm_x4(unsigned r[4], const void* p) {
    asm volatile("ldmatrix.sync.aligned.m8n8.x4.shared.b16 {%0,%1,%2,%3}, [%4];"
                 : "=r"(r[0]), "=r"(r[1]), "=r"(r[2]), "=r"(r[3])
                 : "r"(sptr(p)));
}
__device__ __forceinline__ void mma_tf32(float* c, unsigned a0, unsigned a1, unsigned a2,
                                         unsigned a3, unsigned b0, unsigned b1) {
    asm volatile(
        "mma.sync.aligned.m16n8k8.row.col.f32.tf32.tf32.f32 "
        "{%0,%1,%2,%3}, {%4,%5,%6,%7}, {%8,%9}, {%0,%1,%2,%3};"
        : "+f"(c[0]), "+f"(c[1]), "+f"(c[2]), "+f"(c[3])
        : "r"(a0), "r"(a1), "r"(a2), "r"(a3), "r"(b0), "r"(b1));
}

// fragment compute over one 16-k window at word-offset ko; both operands m-major (TSTR)
__device__ __forceinline__ void fc_mm(const float* As, const float* Bs, int ko,
                                      float (&acc)[2][8][4], int lane, int warpM, int warpN) {
    const int la = lane & 15, ha = (lane >> 4) * 4;
    const int lb = lane & 7, hb = (lane >> 3) * 4;
    unsigned a[2][2][4];
#pragma unroll
    for (int mt = 0; mt < 2; mt++)
#pragma unroll
        for (int kk = 0; kk < 2; kk++)
            ldsm_x4(a[mt][kk], &As[(warpM * 32 + mt * 16 + la) * TSTR + ko + kk * 8 + ha]);
#pragma unroll
    for (int nh = 0; nh < 2; nh++) {
        unsigned b[4][4];
#pragma unroll
        for (int j = 0; j < 4; j++)
            ldsm_x4(b[j], &Bs[(warpN * 64 + nh * 32 + j * 8 + lb) * TSTR + ko + hb]);
#pragma unroll
        for (int kk = 0; kk < 2; kk++)
#pragma unroll
            for (int mt = 0; mt < 2; mt++)
#pragma unroll
                for (int j = 0; j < 4; j++)
                    mma_tf32(acc[mt][nh * 4 + j], a[mt][kk][0], a[mt][kk][1], a[mt][kk][2],
                             a[mt][kk][3], b[j][kk * 2], b[j][kk * 2 + 1]);
    }
}

// ---- r8-proven: bulk-copy double-buffered mainloop (barrier cadence) ----
__device__ __forceinline__ void bulk_mainloop(const float* A, const float* B, int NIT,
                                              float* sh, unsigned mb0, float (&acc)[2][8][4],
                                              int tid, int lane, int warpM, int warpN) {
    const unsigned shu = sptr(sh);
    if (tid == 0) {
        bulk_expect(mb0, 2 * TSLAB_B);
        bulk_cp(shu, A, mb0);
        bulk_cp(shu + 2 * TSLAB_B, B, mb0);
        bulk_expect(mb0 + 8, 2 * TSLAB_B);
        bulk_cp(shu + TSLAB_B, A + TSLAB, mb0 + 8);
        bulk_cp(shu + 3 * TSLAB_B, B + TSLAB, mb0 + 8);
    }
    int ph0 = 0, ph1 = 0;
    for (int it = 0; it < NIT; it++) {
        const int s = it & 1;
        if (s == 0) {
            MBARRIER_WAIT_PARITY(mb0, ph0);
            ph0 ^= 1;
        } else {
            MBARRIER_WAIT_PARITY(mb0 + 8, ph1);
            ph1 ^= 1;
        }
        const float* As = sh + s * TSLAB;
        const float* Bs = sh + 2 * TSLAB + s * TSLAB;
        fc_mm(As, Bs, 0, acc, lane, warpM, warpN);
        fc_mm(As, Bs, 16, acc, lane, warpM, warpN);
        __syncthreads();
        if (it + 2 < NIT && tid == 0) {
            const unsigned mb = mb0 + s * 8;
            bulk_expect(mb, 2 * TSLAB_B);
            bulk_cp(shu + s * TSLAB_B, A + (size_t)(it + 2) * TSLAB, mb);
            bulk_cp(shu + 2 * TSLAB_B + s * TSLAB_B, B + (size_t)(it + 2) * TSLAB, mb);
        }
    }
}

// ---- r10-proven (pw only): 3-buffer producer/consumer ring, no per-iter sync ----
__device__ __forceinline__ void ring_mainloop(const float* A, const float* B, int NIT,
                                              float* sh, unsigned mbF, unsigned mbE,
                                              float (&acc)[2][8][4], int tid, int lane,
                                              int warpM, int warpN) {
    const unsigned shu = sptr(sh);
    if (tid == 0) {
        int npre = NIT < 3 ? NIT : 3;
        for (int s = 0; s < npre; s++) {
            bulk_expect(mbF + s * 8, 2 * TSLAB_B);
            bulk_cp(shu + s * TSLAB_B, A + (size_t)s * TSLAB, mbF + s * 8);
            bulk_cp(shu + (3 + s) * TSLAB_B, B + (size_t)s * TSLAB, mbF + s * 8);
        }
    }
    for (int it = 0; it < NIT; it++) {
        const int j = it % 3;
        const int u = (it / 3) & 1;
        MBARRIER_WAIT_PARITY(mbF + j * 8, u);
        const float* As = sh + j * TSLAB;
        const float* Bs = sh + (3 + j) * TSLAB;
        fc_mm(As, Bs, 0, acc, lane, warpM, warpN);
        fc_mm(As, Bs, 16, acc, lane, warpM, warpN);
        if (lane == 0) MBARRIER_ARRIVE(mbE + j * 8);
        if (tid == 0 && it + 3 < NIT) {
            MBARRIER_WAIT_PARITY(mbE + j * 8, u);
            bulk_expect(mbF + j * 8, 2 * TSLAB_B);
            bulk_cp(shu + j * TSLAB_B, A + (size_t)(it + 3) * TSLAB, mbF + j * 8);
            bulk_cp(shu + (3 + j) * TSLAB_B, B + (size_t)(it + 3) * TSLAB, mbF + j * 8);
        }
    }
    __syncthreads();  // quiesce before epilogue / smem reuse
}

#define GEMM_PROLOG2                                                         \
    extern __shared__ __align__(16) float sh[];                              \
    __shared__ __align__(8) unsigned long long s_mb[2];                      \
    const int tid = threadIdx.x;                                             \
    const int lane = tid & 31, warp = tid >> 5, warpM = warp & 3,            \
              warpN = warp >> 2;                                             \
    const int gid = lane >> 2, tig = lane & 3;                               \
    if (tid == 0) {                                                          \
        MBARRIER_INIT(sptr(&s_mb[0]), 1);                                    \
        MBARRIER_INIT(sptr(&s_mb[1]), 1);                                    \
    }                                                                        \
    __syncthreads();                                                         \
    const unsigned mb0 = sptr(&s_mb[0]);                                     \
    float acc[2][8][4] = {};

#define GEMM_PROLOG_RING                                                     \
    extern __shared__ __align__(16) float sh[];                              \
    __shared__ __align__(8) unsigned long long s_mb[6];                      \
    const int tid = threadIdx.x;                                             \
    const int lane = tid & 31, warp = tid >> 5, warpM = warp & 3,            \
              warpN = warp >> 2;                                             \
    const int gid = lane >> 2, tig = lane & 3;                               \
    if (tid == 0) {                                                          \
        _Pragma("unroll") for (int i = 0; i < 3; i++) {                      \
            MBARRIER_INIT(sptr(&s_mb[i]), 1);                                \
            MBARRIER_INIT(sptr(&s_mb[3 + i]), 8);                            \
        }                                                                    \
    }                                                                        \
    __syncthreads();                                                         \
    const unsigned mbF = sptr(&s_mb[0]);                                     \
    const unsigned mbE = sptr(&s_mb[3]);                                     \
    float acc[2][8][4] = {};

// ---------------- merged weight repack: 4 tensors -> g_wt tiled ----------------
__global__ __launch_bounds__(256) void repack4_kernel(const float* __restrict__ s0,
                                                      const float* __restrict__ s1,
                                                      const float* __restrict__ s2,
                                                      const float* __restrict__ s3) {
    const int which = blockIdx.z >> 2, am = blockIdx.z & 3;
    const float* base = (which == 0) ? s0 : (which == 1) ? s1 : (which == 2) ? s2 : s3;
    const float* s = base + ((size_t)am << 20) + ((size_t)blockIdx.x * 128) * 1024 +
                     blockIdx.y * 32;
    float* d = &g_wt[which][am][(size_t)blockIdx.x * TMB + (size_t)blockIdx.y * TSLAB];
    const int warp = threadIdx.x >> 5, lane = threadIdx.x & 31;
#pragma unroll
    for (int i = 0; i < 16; i++) {
        int r = warp * 16 + i;
        d[r * TSTR + lane] = s[(size_t)r * 1024 + lane];
    }
}

// ---------------- RoPE table init ----------------
__global__ void rope_init_kernel() {
    int idx = blockIdx.x * blockDim.x + threadIdx.x;
    if (idx >= NW * 64) return;
    int w = idx >> 6, j = idx & 63;
    double inv = exp(-((double)(2 * j) / (double)NHD) * log(10000.0));
    double ang = (double)w * inv;
    g_cos[idx] = (float)cos(ang);
    g_sin[idx] = (float)sin(ang);
}

// ---------------- conv 3x3 (16 -> 4) writing tiled-transposed Yt (rows=w, k=h) ------------
__global__ __launch_bounds__(256) void conv_qkv_kernel(
    const float* __restrict__ x,
    const float* __restrict__ wq, const float* __restrict__ bq,
    const float* __restrict__ wk, const float* __restrict__ bk,
    const float* __restrict__ wv, const float* __restrict__ bv) {
    __shared__ float sx[4][18][68];
    __shared__ float sw[3 * 4 * 16 * 9];
    __shared__ float st[16][68];
    const int b = blockIdx.x;
    const int h0 = blockIdx.y * 16;
    const int w0 = blockIdx.z * 64;
    const int tx = threadIdx.x, ty = threadIdx.y;
    const int tid = ty * 16 + tx;

    for (int i = tid; i < 576; i += 256) {
        sw[i] = wq[i];
        sw[576 + i] = wk[i];
        sw[1152 + i] = wv[i];
    }

    float acc[12][4];
#pragma unroll
    for (int o = 0; o < 12; o++)
#pragma unroll
        for (int p = 0; p < 4; p++) acc[o][p] = 0.f;

    for (int cc = 0; cc < 16; cc += 4) {
        __syncthreads();
        for (int e = tid; e < 4 * 18 * 66; e += 256) {
            int ch = e / (18 * 66);
            int r = (e / 66) % 18;
            int cl = e % 66;
            int gh = h0 + r - 1, gw = w0 + cl - 1;
            float v = 0.f;
            if ((unsigned)gh < 1024u && (unsigned)gw < 1024u)
                v = x[(((size_t)(b * 16 + cc + ch)) << 20) + gh * 1024 + gw];
            sx[ch][r][cl] = v;
        }
        __syncthreads();
#pragma unroll
        for (int ch = 0; ch < 4; ch++) {
#pragma unroll
            for (int dy = 0; dy < 3; dy++) {
                float xr[6];
#pragma unroll
                for (int i = 0; i < 6; i++) xr[i] = sx[ch][ty + dy][tx * 4 + i];
#pragma unroll
                for (int dx = 0; dx < 3; dx++) {
                    int widx = (cc + ch) * 9 + dy * 3 + dx;
#pragma unroll
                    for (int o = 0; o < 12; o++) {
                        float wv_ = sw[(o >> 2) * 576 + (o & 3) * 144 + widx];
#pragma unroll
                        for (int p = 0; p < 4; p++) acc[o][p] += wv_ * xr[p + dx];
                    }
                }
            }
        }
    }

    const int wloc = tid >> 2, q = tid & 3;
#pragma unroll
    for (int t = 0; t < 3; t++) {
        const float* bias = (t == 0) ? bq : (t == 1) ? bk : bv;
#pragma unroll
        for (int m = 0; m < 4; m++) {
            float bb = bias[m];
            __syncthreads();
#pragma unroll
            for (int p = 0; p < 4; p++) st[ty][tx * 4 + p] = acc[t * 4 + m][p] + bb;
            __syncthreads();
            float4 v = make_float4(st[q * 4 + 0][wloc], st[q * 4 + 1][wloc],
                                   st[q * 4 + 2][wloc], st[q * 4 + 3][wloc]);
            *(float4*)&g_yt[t][b * 4 + m][tiled_off(w0 + wloc, h0 + q * 4)] = v;
        }
    }
}

// ---------------- pw linear (merged q,k,v; ring): q/k (+rope) -> tiled; v -> V^T tiled ----
__global__ __launch_bounds__(256, 2) void gemm_pw_t() {
    const int m0 = blockIdx.x * 128;  // w
    const int n0 = blockIdx.y * 128;  // f
    const int t = blockIdx.z >> 3;
    const int b4 = blockIdx.z & 7;
    const int am = b4 & 3;
    GEMM_PROLOG_RING;

    const float* A = &g_yt[t][b4][(size_t)(m0 >> 7) * TMB];
    const float* B = &g_wt[t][am][(size_t)(n0 >> 7) * TMB];
    ring_mainloop(A, B, 32, sh, mbF, mbE, acc, tid, lane, warpM, warpN);

    if (t < 2) {
        float* Out = g_qkm[t][b4];
#pragma unroll
        for (int mt = 0; mt < 2; mt++)
#pragma unroll
            for (int half = 0; half < 2; half++) {
                int w = m0 + warpM * 32 + mt * 16 + gid + half * 8;
                size_t rb = (size_t)(w >> 7) * TMB + (w & 127) * TSTR;
#pragma unroll
                for (int nt = 0; nt < 8; nt++) {
                    int f = n0 + warpN * 64 + nt * 8 + 2 * tig;
                    float v0 = acc[mt][nt][half * 2 + 0];
                    float v1 = acc[mt][nt][half * 2 + 1];
                    {
                        int j0 = (f >> 1) & 63;
                        float c = g_cos[w * 64 + j0], s = g_sin[w * 64 + j0];
                        float e = v0 * c - v1 * s, o = v1 * c + v0 * s;
                        v0 = e;
                        v1 = o;
                    }
                    *(float2*)&Out[rb + (size_t)(f >> 5) * TSLAB + (f & 31)] =
                        make_float2(v0, v1);
                }
            }
    } else {
        float* ts = sh;  // reuse mainloop buffers: 128 x 132 transpose stage
#pragma unroll
        for (int mt = 0; mt < 2; mt++)
#pragma unroll
            for (int half = 0; half < 2; half++) {
                int ml = warpM * 32 + mt * 16 + gid + half * 8;
#pragma unroll
                for (int nt = 0; nt < 8; nt++) {
                    int nl = warpN * 64 + nt * 8 + 2 * tig;
                    ts[ml * 132 + nl] = acc[mt][nt][half * 2 + 0];
                    ts[ml * 132 + nl + 1] = acc[mt][nt][half * 2 + 1];
                }
            }
        __syncthreads();
        float* Out = g_vt[b4];
        const int fl = tid >> 1, hf = tid & 1;
        int f = n0 + fl;
        size_t rb = (size_t)(f >> 7) * TMB + (f & 127) * TSTR;
#pragma unroll
        for (int i = 0; i < 64; i += 4) {
            int wl = hf * 64 + i;
            float4 v = make_float4(ts[(wl + 0) * 132 + fl], ts[(wl + 1) * 132 + fl],
                                   ts[(wl + 2) * 132 + fl], ts[(wl + 3) * 132 + fl]);
            int w = m0 + wl;
            *(float4*)&Out[rb + (size_t)(w >> 5) * TSLAB + (w & 31)] = v;
        }
    }
}

// ---------------- qk (Q-resident): S = qk^T/32 + prev + mask; one CTA sweeps all n -------
// grid (8, 64); smem: sQ 4 slabs (resident) + sK 2-slab ring = 6 slabs
__global__ __launch_bounds__(256, 2) void gemm_qk_t(const float* __restrict__ prev_qk,
                                                    const float* __restrict__ mask,
                                                    float* __restrict__ qk_out) {
    const int m0 = blockIdx.x * 128;
    const int bh = blockIdx.y;
    const int b4 = bh >> 3, head = bh & 7;
    extern __shared__ __align__(16) float sh[];
    __shared__ __align__(8) unsigned long long s_mb[3];
    const int tid = threadIdx.x;
    const int lane = tid & 31, warp = tid >> 5, warpM = warp & 3, warpN = warp >> 2;
    const int gid = lane >> 2, tig = lane & 3;

    float* sQ = sh;
    float* sK = sh + 4 * TSLAB;
    const unsigned mbQ = sptr(&s_mb[0]);
    const unsigned mbK = sptr(&s_mb[1]);
    if (tid == 0) {
        MBARRIER_INIT(mbQ, 1);
        MBARRIER_INIT(mbK, 1);
        MBARRIER_INIT(mbK + 8, 1);
    }
    __syncthreads();

    const float* Qb = &g_qkm[0][b4][(size_t)(m0 >> 7) * TMB + (size_t)(head * 4) * TSLAB];
    const float* Kb = &g_qkm[1][b4][(size_t)(head * 4) * TSLAB];  // +nt*TMB + s*TSLAB

    if (tid == 0) {
        bulk_expect(mbQ, 4 * TSLAB_B);
        bulk_cp_n(sptr(sQ), Qb, 4 * TSLAB_B, mbQ);
        bulk_expect(mbK, TSLAB_B);
        bulk_cp(sptr(sK), Kb, mbK);  // g=0: nt=0,s=0
        bulk_expect(mbK + 8, TSLAB_B);
        bulk_cp(sptr(sK) + TSLAB_B, Kb + TSLAB, mbK + 8);  // g=1: nt=0,s=1
    }
    MBARRIER_WAIT_PARITY(mbQ, 0);

    const float* prevb = prev_qk + ((size_t)bh << 20);
    float* outb = qk_out + ((size_t)bh << 20);
    int ph[2] = {0, 0};

    for (int nt = 0; nt < 8; nt++) {
        float acc[2][8][4] = {};
        for (int s = 0; s < 4; s++) {
            const int g = nt * 4 + s;
            const int j = g & 1;
            MBARRIER_WAIT_PARITY(mbK + j * 8, ph[j]);
            ph[j] ^= 1;
            fc_mm(sQ + s * TSLAB, sK + j * TSLAB, 0, acc, lane, warpM, warpN);
            fc_mm(sQ + s * TSLAB, sK + j * TSLAB, 16, acc, lane, warpM, warpN);
            __syncthreads();
            const int g2 = g + 2;
            if (g2 < 32 && tid == 0) {
                const unsigned mb = mbK + j * 8;
                bulk_expect(mb, TSLAB_B);
                bulk_cp(sptr(sK) + j * TSLAB_B,
                        Kb + (size_t)(g2 >> 2) * TMB + (size_t)(g2 & 3) * TSLAB, mb);
            }
        }
        const int n0 = nt * 128;
#pragma unroll
        for (int mt = 0; mt < 2; mt++)
#pragma unroll
            for (int half = 0; half < 2; half++) {
                int mi = m0 + warpM * 32 + mt * 16 + gid + half * 8;
#pragma unroll
                for (int nj = 0; nj < 8; nj++) {
                    int n = n0 + warpN * 64 + nj * 8 + 2 * tig;
                    float2 pv = *(const float2*)&prevb[(size_t)mi * 1024 + n];
                    float2 mk = *(const float2*)&mask[(size_t)mi * 1024 + n];
                    float2 r;
                    r.x = acc[mt][nj][half * 2 + 0] * 0.03125f + pv.x + mk.x;
                    r.y = acc[mt][nj][half * 2 + 1] * 0.03125f + pv.y + mk.y;
                    *(float2*)&outb[(size_t)mi * 1024 + n] = r;
                }
            }
    }
}

// ---------------- pv: A_att = (exp(S) @ V) / rowsum; exp + rowsum computed in-kernel -----
__global__ __launch_bounds__(256, 2) void gemm_pv_t(const float* __restrict__ S) {
    const int m0 = blockIdx.x * 128;
    const int bh = blockIdx.y;
    const int b4 = bh >> 3, head = bh & 7;
    extern __shared__ __align__(16) float sh[];
    __shared__ __align__(8) unsigned long long s_mb[2];
    __shared__ float sred[128];
    const int tid = threadIdx.x;
    const int lane = tid & 31, warp = tid >> 5, warpM = warp & 3, warpN = warp >> 2;
    const int gid = lane >> 2, tig = lane & 3;
    if (tid == 0) {
        MBARRIER_INIT(sptr(&s_mb[0]), 1);
        MBARRIER_INIT(sptr(&s_mb[1]), 1);
    }
    __syncthreads();
    const unsigned mb0 = sptr(&s_mb[0]);
    float acc[2][8][4] = {};

    float* Abuf = sh;                 // 2 x TSLAB: staged exp(S) m-major
    float* Bbuf = sh + 2 * TSLAB;     // 2 x TSLAB: V tiles
    const unsigned shuB = sptr(Bbuf);
    const float* Vb = &g_vt[b4][(size_t)head * TMB];

    if (tid == 0) {
        bulk_expect(mb0, TSLAB_B);
        bulk_cp(shuB, Vb, mb0);
        bulk_expect(mb0 + 8, TSLAB_B);
        bulk_cp(shuB + TSLAB_B, Vb + TSLAB, mb0 + 8);
    }

    const int row = tid >> 1, kh = (tid & 1) * 16;
    const float* Sr = S + ((size_t)bh << 20) + (size_t)(m0 + row) * 1024 + kh;
    float4 p0 = *(const float4*)&Sr[0];
    float4 p1 = *(const float4*)&Sr[4];
    float4 p2 = *(const float4*)&Sr[8];
    float4 p3 = *(const float4*)&Sr[12];
    float rsum = 0.f;
    int ph0 = 0, ph1 = 0;

    for (int it = 0; it < 32; it++) {
        const int s = it & 1;
        if (s == 0) {
            MBARRIER_WAIT_PARITY(mb0, ph0);
            ph0 ^= 1;
        } else {
            MBARRIER_WAIT_PARITY(mb0 + 8, ph1);
            ph1 ^= 1;
        }
        {
            float* dst = Abuf + s * TSLAB + row * TSTR + kh;
            float e0 = __expf(p0.x), e1 = __expf(p0.y), e2 = __expf(p0.z), e3 = __expf(p0.w);
            float e4 = __expf(p1.x), e5 = __expf(p1.y), e6 = __expf(p1.z), e7 = __expf(p1.w);
            float e8 = __expf(p2.x), e9 = __expf(p2.y), ea = __expf(p2.z), eb = __expf(p2.w);
            float ec = __expf(p3.x), ed = __expf(p3.y), ee = __expf(p3.z), ef = __expf(p3.w);
            *(float4*)&dst[0] = make_float4(e0, e1, e2, e3);
            *(float4*)&dst[4] = make_float4(e4, e5, e6, e7);
            *(float4*)&dst[8] = make_float4(e8, e9, ea, eb);
            *(float4*)&dst[12] = make_float4(ec, ed, ee, ef);
            rsum += ((e0 + e1) + (e2 + e3)) + ((e4 + e5) + (e6 + e7)) +
                    ((e8 + e9) + (ea + eb)) + ((ec + ed) + (ee + ef));
        }
        if (it + 1 < 32) {
            const float* Sn = Sr + (size_t)(it + 1) * 32;
            p0 = *(const float4*)&Sn[0];
            p1 = *(const float4*)&Sn[4];
            p2 = *(const float4*)&Sn[8];
            p3 = *(const float4*)&Sn[12];
        }
        __syncthreads();
        fc_mm(Abuf + s * TSLAB, Bbuf + s * TSLAB, 0, acc, lane, warpM, warpN);
        fc_mm(Abuf + s * TSLAB, Bbuf + s * TSLAB, 16, acc, lane, warpM, warpN);
        __syncthreads();
        if (tid == 0 && it + 2 < 32) {
            const unsigned mb = mb0 + s * 8;
            bulk_expect(mb, TSLAB_B);
            bulk_cp(shuB + s * TSLAB_B, Vb + (size_t)(it + 2) * TSLAB, mb);
        }
    }

    rsum += __shfl_xor_sync(0xffffffffu, rsum, 1);
    if ((tid & 1) == 0) sred[row] = 1.0f / rsum;
    __syncthreads();

    float* Ab = g_a[b4];
#pragma unroll
    for (int mt = 0; mt < 2; mt++)
#pragma unroll
        for (int half = 0; half < 2; half++) {
            int ml = warpM * 32 + mt * 16 + gid + half * 8;
            int mi = m0 + ml;
            float rv = sred[ml];
#pragma unroll
            for (int nt = 0; nt < 8; nt++) {
                int n = warpN * 64 + nt * 8 + 2 * tig;
                float2 r = make_float2(acc[mt][nt][half * 2 + 0] * rv,
                                       acc[mt][nt][half * 2 + 1] * rv);
                *(float2*)&Ab[(size_t)mi * 1024 + head * 128 + n] = r;
            }
        }
}

// ---------------- 4x4 depthwise channel mix -> tiled g_aot ----------------
__global__ __launch_bounds__(256) void dw_kernel(const float* __restrict__ dw) {
    int idx = blockIdx.x * 256 + threadIdx.x;
    int b = idx >> 18;
    size_t off = ((size_t)(idx & 262143)) << 2;
    int w = (int)(off >> 10), h = (int)(off & 1023);
    size_t toff = tiled_off(w, h);
    float4 a[4];
#pragma unroll
    for (int c = 0; c < 4; c++) a[c] = *(const float4*)&g_a[b * 4 + c][off];
#pragma unroll
    for (int o = 0; o < 4; o++) {
        float w0 = dw[o * 4 + 0], w1 = dw[o * 4 + 1], w2 = dw[o * 4 + 2], w3 = dw[o * 4 + 3];
        float4 r;
        r.x = w0 * a[0].x + w1 * a[1].x + w2 * a[2].x + w3 * a[3].x;
        r.y = w0 * a[0].y + w1 * a[1].y + w2 * a[2].y + w3 * a[3].y;
        r.z = w0 * a[0].z + w1 * a[1].z + w2 * a[2].z + w3 * a[3].z;
        r.w = w0 * a[0].w + w1 * a[1].w + w2 * a[2].w + w3 * a[3].w;
        *(float4*)&g_aot[b * 4 + o][toff] = r;
    }
}

// ---------------- wo_pw (r8 loop): Out[f][w] = W * Ao^T (plain out) ----------------
__global__ __launch_bounds__(256, 2) void gemm_wo_t() {
    const int m0 = blockIdx.x * 128;  // f
    const int n0 = blockIdx.y * 128;  // w
    const int b4 = blockIdx.z;
    const int am = b4 & 3;
    GEMM_PROLOG2;

    const float* A = &g_wt[3][am][(size_t)(m0 >> 7) * TMB];
    const float* B = &g_aot[b4][(size_t)(n0 >> 7) * TMB];
    bulk_mainloop(A, B, 32, sh, mb0, acc, tid, lane, warpM, warpN);

    float* Out = g_a2[b4];
#pragma unroll
    for (int mt = 0; mt < 2; mt++)
#pragma unroll
        for (int half = 0; half < 2; half++) {
            int mi = m0 + warpM * 32 + mt * 16 + gid + half * 8;
#pragma unroll
            for (int nt = 0; nt < 8; nt++) {
                int n = n0 + warpN * 64 + nt * 8 + 2 * tig;
                float2 r = make_float2(acc[mt][nt][half * 2 + 0], acc[mt][nt][half * 2 + 1]);
                *(float2*)&Out[(size_t)mi * 1024 + n] = r;
            }
        }
}

// ---------------- final conv 3x3 over concat(x[16], a2[4]) -> 16 channels ----------------
__global__ __launch_bounds__(256) void conv_out_kernel(const float* __restrict__ x,
                                                       const float* __restrict__ wo,
                                                       const float* __restrict__ bo,
                                                       float* __restrict__ out) {
    __shared__ float sx[4][18][68];
    __shared__ float sw[16 * 20 * 9];
    const int b = blockIdx.x;
    const int h0 = blockIdx.y * 16;
    const int w0 = blockIdx.z * 64;
    const int tx = threadIdx.x, ty = threadIdx.y;
    const int tid = ty * 16 + tx;

    for (int i = tid; i < 2880; i += 256) sw[i] = wo[i];

    float acc[16][4];
#pragma unroll
    for (int o = 0; o < 16; o++)
#pragma unroll
        for (int p = 0; p < 4; p++) acc[o][p] = 0.f;

    for (int cc = 0; cc < 20; cc += 4) {
        __syncthreads();
        for (int e = tid; e < 4 * 18 * 66; e += 256) {
            int ch = e / (18 * 66);
            int r = (e / 66) % 18;
            int cl = e % 66;
            int gh = h0 + r - 1, gw = w0 + cl - 1;
            int c = cc + ch;
            float v = 0.f;
            if ((unsigned)gh < 1024u && (unsigned)gw < 1024u) {
                const float* src = (c < 16) ? (x + (((size_t)(b * 16 + c)) << 20))
                                            : g_a2[b * 4 + (c - 16)];
                v = src[gh * 1024 + gw];
            }
            sx[ch][r][cl] = v;
        }
        __syncthreads();
#pragma unroll
        for (int ch = 0; ch < 4; ch++) {
#pragma unroll
            for (int dy = 0; dy < 3; dy++) {
                float xr[6];
#pragma unroll
                for (int i = 0; i < 6; i++) xr[i] = sx[ch][ty + dy][tx * 4 + i];
#pragma unroll
                for (int dx = 0; dx < 3; dx++) {
                    int widx = (cc + ch) * 9 + dy * 3 + dx;
#pragma unroll
                    for (int o = 0; o < 16; o++) {
                        float wv_ = sw[o * 180 + widx];
#pragma unroll
                        for (int p = 0; p < 4; p++) acc[o][p] += wv_ * xr[p + dx];
                    }
                }
            }
        }
    }

    int gh = h0 + ty, gw = w0 + tx * 4;
#pragma unroll
    for (int o = 0; o < 16; o++) {
        float bb = bo[o];
        float4 v = make_float4(acc[o][0] + bb, acc[o][1] + bb, acc[o][2] + bb, acc[o][3] + bb);
        *(float4*)&out[(((size_t)(b * 16 + o)) << 20) + gh * 1024 + gw] = v;
    }
}

// ---------------- launch ----------------
extern "C" void kernel_launch(void* const* d_in, const int* in_sizes, int n_in,
                              void* d_out, int out_size) {
    const float* x       = (const float*)d_in[0];
    const float* prev_qk = (const float*)d_in[1];
    const float* mask    = (const float*)d_in[2];
    const float* wq_conv = (const float*)d_in[3];
    const float* bq_conv = (const float*)d_in[4];
    const float* wq_pw   = (const float*)d_in[5];
    const float* wk_conv = (const float*)d_in[6];
    const float* bk_conv = (const float*)d_in[7];
    const float* wk_pw   = (const float*)d_in[8];
    const float* wv_conv = (const float*)d_in[9];
    const float* bv_conv = (const float*)d_in[10];
    const float* wv_pw   = (const float*)d_in[11];
    const float* wo_pw   = (const float*)d_in[12];
    const float* wo_dw   = (const float*)d_in[13];
    const float* wo_conv = (const float*)d_in[14];
    const float* bo_conv = (const float*)d_in[15];

    float* outp = (float*)d_out;                       // (2,16,1024,1024)
    float* qk_out = outp + (size_t)NB * NC * NF * NW;  // (2,4,8,1024,1024)

    const int GM_SM = 4 * TSLAB_B;   // 73728  (pv, wo)
    const int QK_SM = 6 * TSLAB_B;   // 110592 (Q-resident qk; 2 CTAs/SM)
    const int PW_SM = 6 * TSLAB_B;   // 110592 (ring pw; 2 CTAs/SM)

    cudaFuncSetAttribute(gemm_pw_t, cudaFuncAttributeMaxDynamicSharedMemorySize, PW_SM);
    cudaFuncSetAttribute(gemm_qk_t, cudaFuncAttributeMaxDynamicSharedMemorySize, QK_SM);
    cudaFuncSetAttribute(gemm_pv_t, cudaFuncAttributeMaxDynamicSharedMemorySize, GM_SM);
    cudaFuncSetAttribute(gemm_wo_t, cudaFuncAttributeMaxDynamicSharedMemorySize, GM_SM);

    rope_init_kernel<<<64, 1024>>>();
    repack4_kernel<<<dim3(8, 32, 16), 256>>>(wq_pw, wk_pw, wv_pw, wo_pw);
    conv_qkv_kernel<<<dim3(NB, 64, 16), dim3(16, 16)>>>(x, wq_conv, bq_conv,
                                                        wk_conv, bk_conv, wv_conv, bv_conv);
    gemm_pw_t<<<dim3(8, 8, 24), 256, PW_SM>>>();
    gemm_qk_t<<<dim3(8, 64), 256, QK_SM>>>(prev_qk, mask, qk_out);
    gemm_pv_t<<<dim3(8, 64), 256, GM_SM>>>(qk_out);
    dw_kernel<<<2048, 256>>>(wo_dw);
    gemm_wo_t<<<dim3(8, 8, 8), 256, GM_SM>>>();
    conv_out_kernel<<<dim3(NB, 64, 16), dim3(16, 16)>>>(x, wo_conv, bo_conv, outp);
}

// round 15
// speedup vs baseline: 1.0498x; 1.0498x over previous
#include <cuda_runtime.h>
#include <math.h>

// Problem dims
#define NB 2
#define NC 16
#define NAM 4
#define NHEADS 8
#define NF 1024
#define NW 1024
#define NHD 128

// Tiled-slab layout: slab = 128 rows x 32 k, rows padded to 36 words -> 18432B contiguous
#define TSTR 36
#define TSLAB 4608
#define TSLAB_B 18432u
#define TMB 147456
#define TMAT 1179648

// ---------------- scratch (device globals; no runtime allocation) ----------------
__device__ float g_yt[3][8][TMAT];      // conv outputs tiled: rows=w, k=h
__device__ float g_qkm[2][8][TMAT];     // q,k tiled: rows=w, k=f
__device__ float g_vt[8][TMAT];         // V^T tiled: rows=f, k=w
__device__ float g_wt[4][4][TMAT];      // repacked weights [q,k,v,o][am]: rows=f, k=h
__device__ float g_aot[8][TMAT];        // after dw mix tiled: rows=w, k=h
__device__ float g_a[8][NW * NF];       // attention out plain [w][f]
__device__ float g_a2[8][NF * NW];      // after wo_pw plain [f][w]
__device__ float g_cos[NW * (NHD / 2)];
__device__ float g_sin[NW * (NHD / 2)];

// ---------------- helpers ----------------
__device__ __forceinline__ unsigned sptr(const void* p) {
    return (unsigned)__cvta_generic_to_shared(p);
}
__device__ __forceinline__ size_t tiled_off(int row, int k) {
    return (size_t)(row >> 7) * TMB + (size_t)(k >> 5) * TSLAB + (row & 127) * TSTR + (k & 31);
}

#define MBARRIER_INIT(addr, count) \
    asm volatile("mbarrier.init.shared.b64 [%0], %1;" ::"r"(addr), "r"(count) : "memory")

#define MBARRIER_WAIT_PARITY(addr, parity)                                              \
    do {                                                                                \
        unsigned _mb = (addr), _pa = (parity), _done;                                   \
        asm volatile(                                                                   \
            "{\n\t.reg .pred p;\n\t"                                                    \
            "mbarrier.try_wait.parity.acquire.cta.shared::cta.b64 p, [%1], %2;\n\t"     \
            "selp.b32 %0, 1, 0, p;\n\t}"                                                \
            : "=r"(_done) : "r"(_mb), "r"(_pa) : "memory");                             \
        if (!_done) {                                                                   \
            asm volatile(                                                               \
                "{\n\t.reg .pred P1;\n\t"                                               \
                "WL_%=:\n\t"                                                            \
                "mbarrier.try_wait.parity.acquire.cta.shared::cta.b64 P1, [%0], %1, 0x989680;\n\t" \
                "@P1 bra.uni WD_%=;\n\t"                                                \
                "bra.uni WL_%=;\n\t"                                                    \
                "WD_%=:\n\t}" ::"r"(_mb), "r"(_pa) : "memory");                         \
        }                                                                               \
    } while (0)

#define MBARRIER_ARRIVE(addr) \
    asm volatile("mbarrier.arrive.shared.b64 _, [%0];" ::"r"(addr) : "memory")

__device__ __forceinline__ void bulk_expect(unsigned mb, unsigned bytes) {
    asm volatile("mbarrier.arrive.expect_tx.shared.b64 _, [%0], %1;" ::"r"(mb), "r"(bytes)
                 : "memory");
}
__device__ __forceinline__ void bulk_cp(unsigned dst, const float* src, unsigned mb) {
    asm volatile(
        "cp.async.bulk.shared::cta.global.mbarrier::complete_tx::bytes [%0], [%1], %2, [%3];"
        ::"r"(dst), "l"(src), "r"(TSLAB_B), "r"(mb)
        : "memory");
}

__device__ __forceinline__ void ldsm_x4(unsigned r[4], const void* p) {
    asm volatile("ldmatrix.sync.aligned.m8n8.x4.shared.b16 {%0,%1,%2,%3}, [%4];"
                 : "=r"(r[0]), "=r"(r[1]), "=r"(r[2]), "=r"(r[3])
                 : "r"(sptr(p)));
}
__device__ __forceinline__ void mma_tf32(float* c, unsigned a0, unsigned a1, unsigned a2,
                                         unsigned a3, unsigned b0, unsigned b1) {
    asm volatile(
        "mma.sync.aligned.m16n8k8.row.col.f32.tf32.tf32.f32 "
        "{%0,%1,%2,%3}, {%4,%5,%6,%7}, {%8,%9}, {%0,%1,%2,%3};"
        : "+f"(c[0]), "+f"(c[1]), "+f"(c[2]), "+f"(c[3])
        : "r"(a0), "r"(a1), "r"(a2), "r"(a3), "r"(b0), "r"(b1));
}

// fragment compute over one 16-k window at word-offset ko; both operands m-major (TSTR)
__device__ __forceinline__ void fc_mm(const float* As, const float* Bs, int ko,
                                      float (&acc)[2][8][4], int lane, int warpM, int warpN) {
    const int la = lane & 15, ha = (lane >> 4) * 4;
    const int lb = lane & 7, hb = (lane >> 3) * 4;
    unsigned a[2][2][4];
#pragma unroll
    for (int mt = 0; mt < 2; mt++)
#pragma unroll
        for (int kk = 0; kk < 2; kk++)
            ldsm_x4(a[mt][kk], &As[(warpM * 32 + mt * 16 + la) * TSTR + ko + kk * 8 + ha]);
#pragma unroll
    for (int nh = 0; nh < 2; nh++) {
        unsigned b[4][4];
#pragma unroll
        for (int j = 0; j < 4; j++)
            ldsm_x4(b[j], &Bs[(warpN * 64 + nh * 32 + j * 8 + lb) * TSTR + ko + hb]);
#pragma unroll
        for (int kk = 0; kk < 2; kk++)
#pragma unroll
            for (int mt = 0; mt < 2; mt++)
#pragma unroll
                for (int j = 0; j < 4; j++)
                    mma_tf32(acc[mt][nh * 4 + j], a[mt][kk][0], a[mt][kk][1], a[mt][kk][2],
                             a[mt][kk][3], b[j][kk * 2], b[j][kk * 2 + 1]);
    }
}

// ---- r8-proven: bulk-copy double-buffered mainloop (barrier cadence) ----
__device__ __forceinline__ void bulk_mainloop(const float* A, const float* B, int NIT,
                                              float* sh, unsigned mb0, float (&acc)[2][8][4],
                                              int tid, int lane, int warpM, int warpN) {
    const unsigned shu = sptr(sh);
    if (tid == 0) {
        bulk_expect(mb0, 2 * TSLAB_B);
        bulk_cp(shu, A, mb0);
        bulk_cp(shu + 2 * TSLAB_B, B, mb0);
        bulk_expect(mb0 + 8, 2 * TSLAB_B);
        bulk_cp(shu + TSLAB_B, A + TSLAB, mb0 + 8);
        bulk_cp(shu + 3 * TSLAB_B, B + TSLAB, mb0 + 8);
    }
    int ph0 = 0, ph1 = 0;
    for (int it = 0; it < NIT; it++) {
        const int s = it & 1;
        if (s == 0) {
            MBARRIER_WAIT_PARITY(mb0, ph0);
            ph0 ^= 1;
        } else {
            MBARRIER_WAIT_PARITY(mb0 + 8, ph1);
            ph1 ^= 1;
        }
        const float* As = sh + s * TSLAB;
        const float* Bs = sh + 2 * TSLAB + s * TSLAB;
        fc_mm(As, Bs, 0, acc, lane, warpM, warpN);
        fc_mm(As, Bs, 16, acc, lane, warpM, warpN);
        __syncthreads();
        if (it + 2 < NIT && tid == 0) {
            const unsigned mb = mb0 + s * 8;
            bulk_expect(mb, 2 * TSLAB_B);
            bulk_cp(shu + s * TSLAB_B, A + (size_t)(it + 2) * TSLAB, mb);
            bulk_cp(shu + 2 * TSLAB_B + s * TSLAB_B, B + (size_t)(it + 2) * TSLAB, mb);
        }
    }
}

// ---- r10-proven (pw only): 3-buffer producer/consumer ring, no per-iter sync ----
__device__ __forceinline__ void ring_mainloop(const float* A, const float* B, int NIT,
                                              float* sh, unsigned mbF, unsigned mbE,
                                              float (&acc)[2][8][4], int tid, int lane,
                                              int warpM, int warpN) {
    const unsigned shu = sptr(sh);
    if (tid == 0) {
        int npre = NIT < 3 ? NIT : 3;
        for (int s = 0; s < npre; s++) {
            bulk_expect(mbF + s * 8, 2 * TSLAB_B);
            bulk_cp(shu + s * TSLAB_B, A + (size_t)s * TSLAB, mbF + s * 8);
            bulk_cp(shu + (3 + s) * TSLAB_B, B + (size_t)s * TSLAB, mbF + s * 8);
        }
    }
    for (int it = 0; it < NIT; it++) {
        const int j = it % 3;
        const int u = (it / 3) & 1;
        MBARRIER_WAIT_PARITY(mbF + j * 8, u);
        const float* As = sh + j * TSLAB;
        const float* Bs = sh + (3 + j) * TSLAB;
        fc_mm(As, Bs, 0, acc, lane, warpM, warpN);
        fc_mm(As, Bs, 16, acc, lane, warpM, warpN);
        if (lane == 0) MBARRIER_ARRIVE(mbE + j * 8);
        if (tid == 0 && it + 3 < NIT) {
            MBARRIER_WAIT_PARITY(mbE + j * 8, u);
            bulk_expect(mbF + j * 8, 2 * TSLAB_B);
            bulk_cp(shu + j * TSLAB_B, A + (size_t)(it + 3) * TSLAB, mbF + j * 8);
            bulk_cp(shu + (3 + j) * TSLAB_B, B + (size_t)(it + 3) * TSLAB, mbF + j * 8);
        }
    }
    __syncthreads();  // quiesce before epilogue / smem reuse
}

#define GEMM_PROLOG2                                                         \
    extern __shared__ __align__(16) float sh[];                              \
    __shared__ __align__(8) unsigned long long s_mb[2];                      \
    const int tid = threadIdx.x;                                             \
    const int lane = tid & 31, warp = tid >> 5, warpM = warp & 3,            \
              warpN = warp >> 2;                                             \
    const int gid = lane >> 2, tig = lane & 3;                               \
    if (tid == 0) {                                                          \
        MBARRIER_INIT(sptr(&s_mb[0]), 1);                                    \
        MBARRIER_INIT(sptr(&s_mb[1]), 1);                                    \
    }                                                                        \
    __syncthreads();                                                         \
    const unsigned mb0 = sptr(&s_mb[0]);                                     \
    float acc[2][8][4] = {};

#define GEMM_PROLOG_RING                                                     \
    extern __shared__ __align__(16) float sh[];                              \
    __shared__ __align__(8) unsigned long long s_mb[6];                      \
    const int tid = threadIdx.x;                                             \
    const int lane = tid & 31, warp = tid >> 5, warpM = warp & 3,            \
              warpN = warp >> 2;                                             \
    const int gid = lane >> 2, tig = lane & 3;                               \
    if (tid == 0) {                                                          \
        _Pragma("unroll") for (int i = 0; i < 3; i++) {                      \
            MBARRIER_INIT(sptr(&s_mb[i]), 1);                                \
            MBARRIER_INIT(sptr(&s_mb[3 + i]), 8);                            \
        }                                                                    \
    }                                                                        \
    __syncthreads();                                                         \
    const unsigned mbF = sptr(&s_mb[0]);                                     \
    const unsigned mbE = sptr(&s_mb[3]);                                     \
    float acc[2][8][4] = {};

// ---------------- merged weight repack: 4 tensors -> g_wt tiled ----------------
__global__ __launch_bounds__(256) void repack4_kernel(const float* __restrict__ s0,
                                                      const float* __restrict__ s1,
                                                      const float* __restrict__ s2,
                                                      const float* __restrict__ s3) {
    const int which = blockIdx.z >> 2, am = blockIdx.z & 3;
    const float* base = (which == 0) ? s0 : (which == 1) ? s1 : (which == 2) ? s2 : s3;
    const float* s = base + ((size_t)am << 20) + ((size_t)blockIdx.x * 128) * 1024 +
                     blockIdx.y * 32;
    float* d = &g_wt[which][am][(size_t)blockIdx.x * TMB + (size_t)blockIdx.y * TSLAB];
    const int warp = threadIdx.x >> 5, lane = threadIdx.x & 31;
#pragma unroll
    for (int i = 0; i < 16; i++) {
        int r = warp * 16 + i;
        d[r * TSTR + lane] = s[(size_t)r * 1024 + lane];
    }
}

// ---------------- RoPE table init: fp64 angle, fp32 trig; chip-filling grid ----------------
__global__ void rope_init_kernel() {
    int idx = blockIdx.x * blockDim.x + threadIdx.x;
    if (idx >= NW * 64) return;
    int w = idx >> 6, j = idx & 63;
    double inv = exp(-((double)(2 * j) / (double)NHD) * log(10000.0));
    float ang = (float)((double)w * inv);
    g_cos[idx] = cosf(ang);
    g_sin[idx] = sinf(ang);
}

// ---------------- conv 3x3 (16 -> 4) writing tiled-transposed Yt (rows=w, k=h) ------------
__global__ __launch_bounds__(256) void conv_qkv_kernel(
    const float* __restrict__ x,
    const float* __restrict__ wq, const float* __restrict__ bq,
    const float* __restrict__ wk, const float* __restrict__ bk,
    const float* __restrict__ wv, const float* __restrict__ bv) {
    __shared__ float sx[4][18][68];
    __shared__ float sw[3 * 4 * 16 * 9];
    __shared__ float st4[4][16][68];
    const int b = blockIdx.x;
    const int h0 = blockIdx.y * 16;
    const int w0 = blockIdx.z * 64;
    const int tx = threadIdx.x, ty = threadIdx.y;
    const int tid = ty * 16 + tx;

    for (int i = tid; i < 576; i += 256) {
        sw[i] = wq[i];
        sw[576 + i] = wk[i];
        sw[1152 + i] = wv[i];
    }

    float acc[12][4];
#pragma unroll
    for (int o = 0; o < 12; o++)
#pragma unroll
        for (int p = 0; p < 4; p++) acc[o][p] = 0.f;

    for (int cc = 0; cc < 16; cc += 4) {
        __syncthreads();
        for (int e = tid; e < 4 * 18 * 66; e += 256) {
            int ch = e / (18 * 66);
            int r = (e / 66) % 18;
            int cl = e % 66;
            int gh = h0 + r - 1, gw = w0 + cl - 1;
            float v = 0.f;
            if ((unsigned)gh < 1024u && (unsigned)gw < 1024u)
                v = x[(((size_t)(b * 16 + cc + ch)) << 20) + gh * 1024 + gw];
            sx[ch][r][cl] = v;
        }
        __syncthreads();
#pragma unroll
        for (int ch = 0; ch < 4; ch++) {
#pragma unroll
            for (int dy = 0; dy < 3; dy++) {
                float xr[6];
#pragma unroll
                for (int i = 0; i < 6; i++) xr[i] = sx[ch][ty + dy][tx * 4 + i];
#pragma unroll
                for (int dx = 0; dx < 3; dx++) {
                    int widx = (cc + ch) * 9 + dy * 3 + dx;
#pragma unroll
                    for (int o = 0; o < 12; o++) {
                        float wv_ = sw[(o >> 2) * 576 + (o & 3) * 144 + widx];
#pragma unroll
                        for (int p = 0; p < 4; p++) acc[o][p] += wv_ * xr[p + dx];
                    }
                }
            }
        }
    }

    // batched transposed store: 4 maps (one tensor t) per stage -> 6 syncs total
    const int wloc = tid >> 2, q = tid & 3;
#pragma unroll
    for (int t = 0; t < 3; t++) {
        const float* bias = (t == 0) ? bq : (t == 1) ? bk : bv;
        __syncthreads();
#pragma unroll
        for (int m = 0; m < 4; m++) {
            float bb = bias[m];
#pragma unroll
            for (int p = 0; p < 4; p++) st4[m][ty][tx * 4 + p] = acc[t * 4 + m][p] + bb;
        }
        __syncthreads();
#pragma unroll
        for (int m = 0; m < 4; m++) {
            float4 v = make_float4(st4[m][q * 4 + 0][wloc], st4[m][q * 4 + 1][wloc],
                                   st4[m][q * 4 + 2][wloc], st4[m][q * 4 + 3][wloc]);
            *(float4*)&g_yt[t][b * 4 + m][tiled_off(w0 + wloc, h0 + q * 4)] = v;
        }
    }
}

// ---------------- pw linear (merged q,k,v; ring): q/k (+rope) -> tiled; v -> V^T tiled ----
__global__ __launch_bounds__(256, 2) void gemm_pw_t() {
    const int m0 = blockIdx.x * 128;  // w
    const int n0 = blockIdx.y * 128;  // f
    const int t = blockIdx.z >> 3;
    const int b4 = blockIdx.z & 7;
    const int am = b4 & 3;
    GEMM_PROLOG_RING;

    const float* A = &g_yt[t][b4][(size_t)(m0 >> 7) * TMB];
    const float* B = &g_wt[t][am][(size_t)(n0 >> 7) * TMB];
    ring_mainloop(A, B, 32, sh, mbF, mbE, acc, tid, lane, warpM, warpN);

    if (t < 2) {
        float* Out = g_qkm[t][b4];
#pragma unroll
        for (int mt = 0; mt < 2; mt++)
#pragma unroll
            for (int half = 0; half < 2; half++) {
                int w = m0 + warpM * 32 + mt * 16 + gid + half * 8;
                size_t rb = (size_t)(w >> 7) * TMB + (w & 127) * TSTR;
#pragma unroll
                for (int nt = 0; nt < 8; nt++) {
                    int f = n0 + warpN * 64 + nt * 8 + 2 * tig;
                    float v0 = acc[mt][nt][half * 2 + 0];
                    float v1 = acc[mt][nt][half * 2 + 1];
                    {
                        int j0 = (f >> 1) & 63;
                        float c = g_cos[w * 64 + j0], s = g_sin[w * 64 + j0];
                        float e = v0 * c - v1 * s, o = v1 * c + v0 * s;
                        v0 = e;
                        v1 = o;
                    }
                    *(float2*)&Out[rb + (size_t)(f >> 5) * TSLAB + (f & 31)] =
                        make_float2(v0, v1);
                }
            }
    } else {
        float* ts = sh;  // reuse mainloop buffers: 128 x 132 transpose stage
#pragma unroll
        for (int mt = 0; mt < 2; mt++)
#pragma unroll
            for (int half = 0; half < 2; half++) {
                int ml = warpM * 32 + mt * 16 + gid + half * 8;
#pragma unroll
                for (int nt = 0; nt < 8; nt++) {
                    int nl = warpN * 64 + nt * 8 + 2 * tig;
                    ts[ml * 132 + nl] = acc[mt][nt][half * 2 + 0];
                    ts[ml * 132 + nl + 1] = acc[mt][nt][half * 2 + 1];
                }
            }
        __syncthreads();
        float* Out = g_vt[b4];
        const int fl = tid >> 1, hf = tid & 1;
        int f = n0 + fl;
        size_t rb = (size_t)(f >> 7) * TMB + (f & 127) * TSTR;
#pragma unroll
        for (int i = 0; i < 64; i += 4) {
            int wl = hf * 64 + i;
            float4 v = make_float4(ts[(wl + 0) * 132 + fl], ts[(wl + 1) * 132 + fl],
                                   ts[(wl + 2) * 132 + fl], ts[(wl + 3) * 132 + fl]);
            int w = m0 + wl;
            *(float4*)&Out[rb + (size_t)(w >> 5) * TSLAB + (w & 31)] = v;
        }
    }
}

// ---------------- qk (r8 loop): S = qk^T/32 + prev + mask (S only) ----------------
__global__ __launch_bounds__(256, 2) void gemm_qk_t(const float* __restrict__ prev_qk,
                                                    const float* __restrict__ mask,
                                                    float* __restrict__ qk_out) {
    const int m0 = blockIdx.x * 128;
    const int n0 = blockIdx.y * 128;
    const int bh = blockIdx.z;
    const int b4 = bh >> 3, head = bh & 7;
    GEMM_PROLOG2;

    const float* A = &g_qkm[0][b4][(size_t)(m0 >> 7) * TMB + (size_t)(head * 4) * TSLAB];
    const float* B = &g_qkm[1][b4][(size_t)(n0 >> 7) * TMB + (size_t)(head * 4) * TSLAB];
    bulk_mainloop(A, B, 4, sh, mb0, acc, tid, lane, warpM, warpN);

    const float* prevb = prev_qk + ((size_t)bh << 20);
    float* outb = qk_out + ((size_t)bh << 20);
#pragma unroll
    for (int mt = 0; mt < 2; mt++)
#pragma unroll
        for (int half = 0; half < 2; half++) {
            int mi = m0 + warpM * 32 + mt * 16 + gid + half * 8;
#pragma unroll
            for (int nt = 0; nt < 8; nt++) {
                int n = n0 + warpN * 64 + nt * 8 + 2 * tig;
                float2 pv = *(const float2*)&prevb[(size_t)mi * 1024 + n];
                float2 mk = *(const float2*)&mask[(size_t)mi * 1024 + n];
                float2 r;
                r.x = acc[mt][nt][half * 2 + 0] * 0.03125f + pv.x + mk.x;
                r.y = acc[mt][nt][half * 2 + 1] * 0.03125f + pv.y + mk.y;
                *(float2*)&outb[(size_t)mi * 1024 + n] = r;
            }
        }
}

// ---------------- pv: A_att = (exp(S) @ V) / rowsum; exp + rowsum computed in-kernel -----
__global__ __launch_bounds__(256, 2) void gemm_pv_t(const float* __restrict__ S) {
    const int m0 = blockIdx.x * 128;
    const int bh = blockIdx.y;
    const int b4 = bh >> 3, head = bh & 7;
    extern __shared__ __align__(16) float sh[];
    __shared__ __align__(8) unsigned long long s_mb[2];
    __shared__ float sred[128];
    const int tid = threadIdx.x;
    const int lane = tid & 31, warp = tid >> 5, warpM = warp & 3, warpN = warp >> 2;
    const int gid = lane >> 2, tig = lane & 3;
    if (tid == 0) {
        MBARRIER_INIT(sptr(&s_mb[0]), 1);
        MBARRIER_INIT(sptr(&s_mb[1]), 1);
    }
    __syncthreads();
    const unsigned mb0 = sptr(&s_mb[0]);
    float acc[2][8][4] = {};

    float* Abuf = sh;                 // 2 x TSLAB: staged exp(S) m-major
    float* Bbuf = sh + 2 * TSLAB;     // 2 x TSLAB: V tiles
    const unsigned shuB = sptr(Bbuf);
    const float* Vb = &g_vt[b4][(size_t)head * TMB];

    if (tid == 0) {
        bulk_expect(mb0, TSLAB_B);
        bulk_cp(shuB, Vb, mb0);
        bulk_expect(mb0 + 8, TSLAB_B);
        bulk_cp(shuB + TSLAB_B, Vb + TSLAB, mb0 + 8);
    }

    const int row = tid >> 1, kh = (tid & 1) * 16;
    const float* Sr = S + ((size_t)bh << 20) + (size_t)(m0 + row) * 1024 + kh;
    float4 p0 = *(const float4*)&Sr[0];
    float4 p1 = *(const float4*)&Sr[4];
    float4 p2 = *(const float4*)&Sr[8];
    float4 p3 = *(const float4*)&Sr[12];
    float rsum = 0.f;
    int ph0 = 0, ph1 = 0;

    for (int it = 0; it < 32; it++) {
        const int s = it & 1;
        if (s == 0) {
            MBARRIER_WAIT_PARITY(mb0, ph0);
            ph0 ^= 1;
        } else {
            MBARRIER_WAIT_PARITY(mb0 + 8, ph1);
            ph1 ^= 1;
        }
        {
            float* dst = Abuf + s * TSLAB + row * TSTR + kh;
            float e0 = __expf(p0.x), e1 = __expf(p0.y), e2 = __expf(p0.z), e3 = __expf(p0.w);
            float e4 = __expf(p1.x), e5 = __expf(p1.y), e6 = __expf(p1.z), e7 = __expf(p1.w);
            float e8 = __expf(p2.x), e9 = __expf(p2.y), ea = __expf(p2.z), eb = __expf(p2.w);
            float ec = __expf(p3.x), ed = __expf(p3.y), ee = __expf(p3.z), ef = __expf(p3.w);
            *(float4*)&dst[0] = make_float4(e0, e1, e2, e3);
            *(float4*)&dst[4] = make_float4(e4, e5, e6, e7);
            *(float4*)&dst[8] = make_float4(e8, e9, ea, eb);
            *(float4*)&dst[12] = make_float4(ec, ed, ee, ef);
            rsum += ((e0 + e1) + (e2 + e3)) + ((e4 + e5) + (e6 + e7)) +
                    ((e8 + e9) + (ea + eb)) + ((ec + ed) + (ee + ef));
        }
        if (it + 1 < 32) {
            const float* Sn = Sr + (size_t)(it + 1) * 32;
            p0 = *(const float4*)&Sn[0];
            p1 = *(const float4*)&Sn[4];
            p2 = *(const float4*)&Sn[8];
            p3 = *(const float4*)&Sn[12];
        }
        __syncthreads();
        fc_mm(Abuf + s * TSLAB, Bbuf + s * TSLAB, 0, acc, lane, warpM, warpN);
        fc_mm(Abuf + s * TSLAB, Bbuf + s * TSLAB, 16, acc, lane, warpM, warpN);
        __syncthreads();
        if (tid == 0 && it + 2 < 32) {
            const unsigned mb = mb0 + s * 8;
            bulk_expect(mb, TSLAB_B);
            bulk_cp(shuB + s * TSLAB_B, Vb + (size_t)(it + 2) * TSLAB, mb);
        }
    }

    rsum += __shfl_xor_sync(0xffffffffu, rsum, 1);
    if ((tid & 1) == 0) sred[row] = 1.0f / rsum;
    __syncthreads();

    float* Ab = g_a[b4];
#pragma unroll
    for (int mt = 0; mt < 2; mt++)
#pragma unroll
        for (int half = 0; half < 2; half++) {
            int ml = warpM * 32 + mt * 16 + gid + half * 8;
            int mi = m0 + ml;
            float rv = sred[ml];
#pragma unroll
            for (int nt = 0; nt < 8; nt++) {
                int n = warpN * 64 + nt * 8 + 2 * tig;
                float2 r = make_float2(acc[mt][nt][half * 2 + 0] * rv,
                                       acc[mt][nt][half * 2 + 1] * rv);
                *(float2*)&Ab[(size_t)mi * 1024 + head * 128 + n] = r;
            }
        }
}

// ---------------- 4x4 depthwise channel mix -> tiled g_aot ----------------
__global__ __launch_bounds__(256) void dw_kernel(const float* __restrict__ dw) {
    int idx = blockIdx.x * 256 + threadIdx.x;
    int b = idx >> 18;
    size_t off = ((size_t)(idx & 262143)) << 2;
    int w = (int)(off >> 10), h = (int)(off & 1023);
    size_t toff = tiled_off(w, h);
    float4 a[4];
#pragma unroll
    for (int c = 0; c < 4; c++) a[c] = *(const float4*)&g_a[b * 4 + c][off];
#pragma unroll
    for (int o = 0; o < 4; o++) {
        float w0 = dw[o * 4 + 0], w1 = dw[o * 4 + 1], w2 = dw[o * 4 + 2], w3 = dw[o * 4 + 3];
        float4 r;
        r.x = w0 * a[0].x + w1 * a[1].x + w2 * a[2].x + w3 * a[3].x;
        r.y = w0 * a[0].y + w1 * a[1].y + w2 * a[2].y + w3 * a[3].y;
        r.z = w0 * a[0].z + w1 * a[1].z + w2 * a[2].z + w3 * a[3].z;
        r.w = w0 * a[0].w + w1 * a[1].w + w2 * a[2].w + w3 * a[3].w;
        *(float4*)&g_aot[b * 4 + o][toff] = r;
    }
}

// ---------------- wo_pw (r8 loop): Out[f][w] = W * Ao^T (plain out) ----------------
__global__ __launch_bounds__(256, 2) void gemm_wo_t() {
    const int m0 = blockIdx.x * 128;  // f
    const int n0 = blockIdx.y * 128;  // w
    const int b4 = blockIdx.z;
    const int am = b4 & 3;
    GEMM_PROLOG2;

    const float* A = &g_wt[3][am][(size_t)(m0 >> 7) * TMB];
    const float* B = &g_aot[b4][(size_t)(n0 >> 7) * TMB];
    bulk_mainloop(A, B, 32, sh, mb0, acc, tid, lane, warpM, warpN);

    float* Out = g_a2[b4];
#pragma unroll
    for (int mt = 0; mt < 2; mt++)
#pragma unroll
        for (int half = 0; half < 2; half++) {
            int mi = m0 + warpM * 32 + mt * 16 + gid + half * 8;
#pragma unroll
            for (int nt = 0; nt < 8; nt++) {
                int n = n0 + warpN * 64 + nt * 8 + 2 * tig;
                float2 r = make_float2(acc[mt][nt][half * 2 + 0], acc[mt][nt][half * 2 + 1]);
                *(float2*)&Out[(size_t)mi * 1024 + n] = r;
            }
        }
}

// ---------------- final conv 3x3 over concat(x[16], a2[4]) -> 16 channels ----------------
__global__ __launch_bounds__(256) void conv_out_kernel(const float* __restrict__ x,
                                                       const float* __restrict__ wo,
                                                       const float* __restrict__ bo,
                                                       float* __restrict__ out) {
    __shared__ float sx[4][18][68];
    __shared__ float sw[16 * 20 * 9];
    const int b = blockIdx.x;
    const int h0 = blockIdx.y * 16;
    const int w0 = blockIdx.z * 64;
    const int tx = threadIdx.x, ty = threadIdx.y;
    const int tid = ty * 16 + tx;

    for (int i = tid; i < 2880; i += 256) sw[i] = wo[i];

    float acc[16][4];
#pragma unroll
    for (int o = 0; o < 16; o++)
#pragma unroll
        for (int p = 0; p < 4; p++) acc[o][p] = 0.f;

    for (int cc = 0; cc < 20; cc += 4) {
        __syncthreads();
        for (int e = tid; e < 4 * 18 * 66; e += 256) {
            int ch = e / (18 * 66);
            int r = (e / 66) % 18;
            int cl = e % 66;
            int gh = h0 + r - 1, gw = w0 + cl - 1;
            int c = cc + ch;
            float v = 0.f;
            if ((unsigned)gh < 1024u && (unsigned)gw < 1024u) {
                const float* src = (c < 16) ? (x + (((size_t)(b * 16 + c)) << 20))
                                            : g_a2[b * 4 + (c - 16)];
                v = src[gh * 1024 + gw];
            }
            sx[ch][r][cl] = v;
        }
        __syncthreads();
#pragma unroll
        for (int ch = 0; ch < 4; ch++) {
#pragma unroll
            for (int dy = 0; dy < 3; dy++) {
                float xr[6];
#pragma unroll
                for (int i = 0; i < 6; i++) xr[i] = sx[ch][ty + dy][tx * 4 + i];
#pragma unroll
                for (int dx = 0; dx < 3; dx++) {
                    int widx = (cc + ch) * 9 + dy * 3 + dx;
#pragma unroll
                    for (int o = 0; o < 16; o++) {
                        float wv_ = sw[o * 180 + widx];
#pragma unroll
                        for (int p = 0; p < 4; p++) acc[o][p] += wv_ * xr[p + dx];
                    }
                }
            }
        }
    }

    int gh = h0 + ty, gw = w0 + tx * 4;
#pragma unroll
    for (int o = 0; o < 16; o++) {
        float bb = bo[o];
        float4 v = make_float4(acc[o][0] + bb, acc[o][1] + bb, acc[o][2] + bb, acc[o][3] + bb);
        *(float4*)&out[(((size_t)(b * 16 + o)) << 20) + gh * 1024 + gw] = v;
    }
}

// ---------------- launch ----------------
extern "C" void kernel_launch(void* const* d_in, const int* in_sizes, int n_in,
                              void* d_out, int out_size) {
    const float* x       = (const float*)d_in[0];
    const float* prev_qk = (const float*)d_in[1];
    const float* mask    = (const float*)d_in[2];
    const float* wq_conv = (const float*)d_in[3];
    const float* bq_conv = (const float*)d_in[4];
    const float* wq_pw   = (const float*)d_in[5];
    const float* wk_conv = (const float*)d_in[6];
    const float* bk_conv = (const float*)d_in[7];
    const float* wk_pw   = (const float*)d_in[8];
    const float* wv_conv = (const float*)d_in[9];
    const float* bv_conv = (const float*)d_in[10];
    const float* wv_pw   = (const float*)d_in[11];
    const float* wo_pw   = (const float*)d_in[12];
    const float* wo_dw   = (const float*)d_in[13];
    const float* wo_conv = (const float*)d_in[14];
    const float* bo_conv = (const float*)d_in[15];

    float* outp = (float*)d_out;                       // (2,16,1024,1024)
    float* qk_out = outp + (size_t)NB * NC * NF * NW;  // (2,4,8,1024,1024)

    const int GM_SM = 4 * TSLAB_B;   // 73728  (qk, pv, wo)
    const int PW_SM = 6 * TSLAB_B;   // 110592 (ring pw; 2 CTAs/SM)

    cudaFuncSetAttribute(gemm_pw_t, cudaFuncAttributeMaxDynamicSharedMemorySize, PW_SM);
    cudaFuncSetAttribute(gemm_qk_t, cudaFuncAttributeMaxDynamicSharedMemorySize, GM_SM);
    cudaFuncSetAttribute(gemm_pv_t, cudaFuncAttributeMaxDynamicSharedMemorySize, GM_SM);
    cudaFuncSetAttribute(gemm_wo_t, cudaFuncAttributeMaxDynamicSharedMemorySize, GM_SM);

    rope_init_kernel<<<256, 256>>>();
    repack4_kernel<<<dim3(8, 32, 16), 256>>>(wq_pw, wk_pw, wv_pw, wo_pw);
    conv_qkv_kernel<<<dim3(NB, 64, 16), dim3(16, 16)>>>(x, wq_conv, bq_conv,
                                                        wk_conv, bk_conv, wv_conv, bv_conv);
    gemm_pw_t<<<dim3(8, 8, 24), 256, PW_SM>>>();
    gemm_qk_t<<<dim3(8, 8, 64), 256, GM_SM>>>(prev_qk, mask, qk_out);
    gemm_pv_t<<<dim3(8, 64), 256, GM_SM>>>(qk_out);
    dw_kernel<<<2048, 256>>>(wo_dw);
    gemm_wo_t<<<dim3(8, 8, 8), 256, GM_SM>>>();
    conv_out_kernel<<<dim3(NB, 64, 16), dim3(16, 16)>>>(x, wo_conv, bo_conv, outp);
}

// round 16
// speedup vs baseline: 1.2748x; 1.2144x over previous
#include <cuda_runtime.h>
#include <math.h>

// Problem dims
#define NB 2
#define NC 16
#define NAM 4
#define NHEADS 8
#define NF 1024
#define NW 1024
#define NHD 128

// Tiled-slab layout: slab = 128 rows x 32 k, rows padded to 36 words -> 18432B contiguous
#define TSTR 36
#define TSLAB 4608
#define TSLAB_B 18432u
#define TMB 147456
#define TMAT 1179648

// ---------------- scratch (device globals; no runtime allocation) ----------------
__device__ float g_yt[3][8][TMAT];      // conv outputs tiled: rows=w, k=h
__device__ float g_qkm[2][8][TMAT];     // q,k tiled: rows=w, k=f
__device__ float g_vt[8][TMAT];         // V^T tiled: rows=f, k=w
__device__ float g_wt[4][4][TMAT];      // repacked weights [q,k,v,o][am]: rows=f, k=h
__device__ float g_aot[8][TMAT];        // after dw mix tiled: rows=w, k=h
__device__ float g_a[8][NW * NF];       // attention out plain [w][f]
__device__ float g_a2[8][NF * NW];      // after wo_pw plain [f][w]
__device__ float g_cos[NW * (NHD / 2)];
__device__ float g_sin[NW * (NHD / 2)];

// ---------------- helpers ----------------
__device__ __forceinline__ unsigned sptr(const void* p) {
    return (unsigned)__cvta_generic_to_shared(p);
}
__device__ __forceinline__ size_t tiled_off(int row, int k) {
    return (size_t)(row >> 7) * TMB + (size_t)(k >> 5) * TSLAB + (row & 127) * TSTR + (k & 31);
}

#define MBARRIER_INIT(addr, count) \
    asm volatile("mbarrier.init.shared.b64 [%0], %1;" ::"r"(addr), "r"(count) : "memory")

#define MBARRIER_WAIT_PARITY(addr, parity)                                              \
    do {                                                                                \
        unsigned _mb = (addr), _pa = (parity), _done;                                   \
        asm volatile(                                                                   \
            "{\n\t.reg .pred p;\n\t"                                                    \
            "mbarrier.try_wait.parity.acquire.cta.shared::cta.b64 p, [%1], %2;\n\t"     \
            "selp.b32 %0, 1, 0, p;\n\t}"                                                \
            : "=r"(_done) : "r"(_mb), "r"(_pa) : "memory");                             \
        if (!_done) {                                                                   \
            asm volatile(                                                               \
                "{\n\t.reg .pred P1;\n\t"                                               \
                "WL_%=:\n\t"                                                            \
                "mbarrier.try_wait.parity.acquire.cta.shared::cta.b64 P1, [%0], %1, 0x989680;\n\t" \
                "@P1 bra.uni WD_%=;\n\t"                                                \
                "bra.uni WL_%=;\n\t"                                                    \
                "WD_%=:\n\t}" ::"r"(_mb), "r"(_pa) : "memory");                         \
        }                                                                               \
    } while (0)

#define MBARRIER_ARRIVE(addr) \
    asm volatile("mbarrier.arrive.shared.b64 _, [%0];" ::"r"(addr) : "memory")

__device__ __forceinline__ void bulk_expect(unsigned mb, unsigned bytes) {
    asm volatile("mbarrier.arrive.expect_tx.shared.b64 _, [%0], %1;" ::"r"(mb), "r"(bytes)
                 : "memory");
}
__device__ __forceinline__ void bulk_cp(unsigned dst, const float* src, unsigned mb) {
    asm volatile(
        "cp.async.bulk.shared::cta.global.mbarrier::complete_tx::bytes [%0], [%1], %2, [%3];"
        ::"r"(dst), "l"(src), "r"(TSLAB_B), "r"(mb)
        : "memory");
}

__device__ __forceinline__ void ldsm_x4(unsigned r[4], const void* p) {
    asm volatile("ldmatrix.sync.aligned.m8n8.x4.shared.b16 {%0,%1,%2,%3}, [%4];"
                 : "=r"(r[0]), "=r"(r[1]), "=r"(r[2]), "=r"(r[3])
                 : "r"(sptr(p)));
}
__device__ __forceinline__ void mma_tf32(float* c, unsigned a0, unsigned a1, unsigned a2,
                                         unsigned a3, unsigned b0, unsigned b1) {
    asm volatile(
        "mma.sync.aligned.m16n8k8.row.col.f32.tf32.tf32.f32 "
        "{%0,%1,%2,%3}, {%4,%5,%6,%7}, {%8,%9}, {%0,%1,%2,%3};"
        : "+f"(c[0]), "+f"(c[1]), "+f"(c[2]), "+f"(c[3])
        : "r"(a0), "r"(a1), "r"(a2), "r"(a3), "r"(b0), "r"(b1));
}

// fragment compute over one 16-k window at word-offset ko; both operands m-major (TSTR)
__device__ __forceinline__ void fc_mm(const float* As, const float* Bs, int ko,
                                      float (&acc)[2][8][4], int lane, int warpM, int warpN) {
    const int la = lane & 15, ha = (lane >> 4) * 4;
    const int lb = lane & 7, hb = (lane >> 3) * 4;
    unsigned a[2][2][4];
#pragma unroll
    for (int mt = 0; mt < 2; mt++)
#pragma unroll
        for (int kk = 0; kk < 2; kk++)
            ldsm_x4(a[mt][kk], &As[(warpM * 32 + mt * 16 + la) * TSTR + ko + kk * 8 + ha]);
#pragma unroll
    for (int nh = 0; nh < 2; nh++) {
        unsigned b[4][4];
#pragma unroll
        for (int j = 0; j < 4; j++)
            ldsm_x4(b[j], &Bs[(warpN * 64 + nh * 32 + j * 8 + lb) * TSTR + ko + hb]);
#pragma unroll
        for (int kk = 0; kk < 2; kk++)
#pragma unroll
            for (int mt = 0; mt < 2; mt++)
#pragma unroll
                for (int j = 0; j < 4; j++)
                    mma_tf32(acc[mt][nh * 4 + j], a[mt][kk][0], a[mt][kk][1], a[mt][kk][2],
                             a[mt][kk][3], b[j][kk * 2], b[j][kk * 2 + 1]);
    }
}

// ---- r8-proven: bulk-copy double-buffered mainloop (barrier cadence) ----
__device__ __forceinline__ void bulk_mainloop(const float* A, const float* B, int NIT,
                                              float* sh, unsigned mb0, float (&acc)[2][8][4],
                                              int tid, int lane, int warpM, int warpN) {
    const unsigned shu = sptr(sh);
    if (tid == 0) {
        bulk_expect(mb0, 2 * TSLAB_B);
        bulk_cp(shu, A, mb0);
        bulk_cp(shu + 2 * TSLAB_B, B, mb0);
        bulk_expect(mb0 + 8, 2 * TSLAB_B);
        bulk_cp(shu + TSLAB_B, A + TSLAB, mb0 + 8);
        bulk_cp(shu + 3 * TSLAB_B, B + TSLAB, mb0 + 8);
    }
    int ph0 = 0, ph1 = 0;
    for (int it = 0; it < NIT; it++) {
        const int s = it & 1;
        if (s == 0) {
            MBARRIER_WAIT_PARITY(mb0, ph0);
            ph0 ^= 1;
        } else {
            MBARRIER_WAIT_PARITY(mb0 + 8, ph1);
            ph1 ^= 1;
        }
        const float* As = sh + s * TSLAB;
        const float* Bs = sh + 2 * TSLAB + s * TSLAB;
        fc_mm(As, Bs, 0, acc, lane, warpM, warpN);
        fc_mm(As, Bs, 16, acc, lane, warpM, warpN);
        __syncthreads();
        if (it + 2 < NIT && tid == 0) {
            const unsigned mb = mb0 + s * 8;
            bulk_expect(mb, 2 * TSLAB_B);
            bulk_cp(shu + s * TSLAB_B, A + (size_t)(it + 2) * TSLAB, mb);
            bulk_cp(shu + 2 * TSLAB_B + s * TSLAB_B, B + (size_t)(it + 2) * TSLAB, mb);
        }
    }
}

// ---- r10-proven (pw only): 3-buffer producer/consumer ring, no per-iter sync ----
__device__ __forceinline__ void ring_mainloop(const float* A, const float* B, int NIT,
                                              float* sh, unsigned mbF, unsigned mbE,
                                              float (&acc)[2][8][4], int tid, int lane,
                                              int warpM, int warpN) {
    const unsigned shu = sptr(sh);
    if (tid == 0) {
        int npre = NIT < 3 ? NIT : 3;
        for (int s = 0; s < npre; s++) {
            bulk_expect(mbF + s * 8, 2 * TSLAB_B);
            bulk_cp(shu + s * TSLAB_B, A + (size_t)s * TSLAB, mbF + s * 8);
            bulk_cp(shu + (3 + s) * TSLAB_B, B + (size_t)s * TSLAB, mbF + s * 8);
        }
    }
    for (int it = 0; it < NIT; it++) {
        const int j = it % 3;
        const int u = (it / 3) & 1;
        MBARRIER_WAIT_PARITY(mbF + j * 8, u);
        const float* As = sh + j * TSLAB;
        const float* Bs = sh + (3 + j) * TSLAB;
        fc_mm(As, Bs, 0, acc, lane, warpM, warpN);
        fc_mm(As, Bs, 16, acc, lane, warpM, warpN);
        if (lane == 0) MBARRIER_ARRIVE(mbE + j * 8);
        if (tid == 0 && it + 3 < NIT) {
            MBARRIER_WAIT_PARITY(mbE + j * 8, u);
            bulk_expect(mbF + j * 8, 2 * TSLAB_B);
            bulk_cp(shu + j * TSLAB_B, A + (size_t)(it + 3) * TSLAB, mbF + j * 8);
            bulk_cp(shu + (3 + j) * TSLAB_B, B + (size_t)(it + 3) * TSLAB, mbF + j * 8);
        }
    }
    __syncthreads();  // quiesce before epilogue / smem reuse
}

#define GEMM_PROLOG2                                                         \
    extern __shared__ __align__(16) float sh[];                              \
    __shared__ __align__(8) unsigned long long s_mb[2];                      \
    const int tid = threadIdx.x;                                             \
    const int lane = tid & 31, warp = tid >> 5, warpM = warp & 3,            \
              warpN = warp >> 2;                                             \
    const int gid = lane >> 2, tig = lane & 3;                               \
    if (tid == 0) {                                                          \
        MBARRIER_INIT(sptr(&s_mb[0]), 1);                                    \
        MBARRIER_INIT(sptr(&s_mb[1]), 1);                                    \
    }                                                                        \
    __syncthreads();                                                         \
    const unsigned mb0 = sptr(&s_mb[0]);                                     \
    float acc[2][8][4] = {};

#define GEMM_PROLOG_RING                                                     \
    extern __shared__ __align__(16) float sh[];                              \
    __shared__ __align__(8) unsigned long long s_mb[6];                      \
    const int tid = threadIdx.x;                                             \
    const int lane = tid & 31, warp = tid >> 5, warpM = warp & 3,            \
              warpN = warp >> 2;                                             \
    const int gid = lane >> 2, tig = lane & 3;                               \
    if (tid == 0) {                                                          \
        _Pragma("unroll") for (int i = 0; i < 3; i++) {                      \
            MBARRIER_INIT(sptr(&s_mb[i]), 1);                                \
            MBARRIER_INIT(sptr(&s_mb[3 + i]), 8);                            \
        }                                                                    \
    }                                                                        \
    __syncthreads();                                                         \
    const unsigned mbF = sptr(&s_mb[0]);                                     \
    const unsigned mbE = sptr(&s_mb[3]);                                     \
    float acc[2][8][4] = {};

// ---------------- merged weight repack: 4 tensors -> g_wt tiled ----------------
__global__ __launch_bounds__(256) void repack4_kernel(const float* __restrict__ s0,
                                                      const float* __restrict__ s1,
                                                      const float* __restrict__ s2,
                                                      const float* __restrict__ s3) {
    const int which = blockIdx.z >> 2, am = blockIdx.z & 3;
    const float* base = (which == 0) ? s0 : (which == 1) ? s1 : (which == 2) ? s2 : s3;
    const float* s = base + ((size_t)am << 20) + ((size_t)blockIdx.x * 128) * 1024 +
                     blockIdx.y * 32;
    float* d = &g_wt[which][am][(size_t)blockIdx.x * TMB + (size_t)blockIdx.y * TSLAB];
    const int warp = threadIdx.x >> 5, lane = threadIdx.x & 31;
#pragma unroll
    for (int i = 0; i < 16; i++) {
        int r = warp * 16 + i;
        d[r * TSTR + lane] = s[(size_t)r * 1024 + lane];
    }
}

// ---------------- RoPE table init: fp64 angle, fp32 trig; chip-filling grid ----------------
__global__ void rope_init_kernel() {
    int idx = blockIdx.x * blockDim.x + threadIdx.x;
    if (idx >= NW * 64) return;
    int w = idx >> 6, j = idx & 63;
    double inv = exp(-((double)(2 * j) / (double)NHD) * log(10000.0));
    float ang = (float)((double)w * inv);
    g_cos[idx] = cosf(ang);
    g_sin[idx] = sinf(ang);
}

// ---------------- conv 3x3 (16 -> 4) writing tiled-transposed Yt (rows=w, k=h) ------------
// weights repacked output-major in smem: sw2[t][widx][m] -> one float4 covers 4 maps
__global__ __launch_bounds__(256) void conv_qkv_kernel(
    const float* __restrict__ x,
    const float* __restrict__ wq, const float* __restrict__ bq,
    const float* __restrict__ wk, const float* __restrict__ bk,
    const float* __restrict__ wv, const float* __restrict__ bv) {
    __shared__ __align__(16) float sx[4][18][68];
    __shared__ __align__(16) float sw2[3][144][4];
    __shared__ __align__(16) float st4[4][16][68];
    const int b = blockIdx.x;
    const int h0 = blockIdx.y * 16;
    const int w0 = blockIdx.z * 64;
    const int tx = threadIdx.x, ty = threadIdx.y;
    const int tid = ty * 16 + tx;

    for (int i = tid; i < 576; i += 256) {
        int m = i / 144, widx = i % 144;
        sw2[0][widx][m] = wq[i];
        sw2[1][widx][m] = wk[i];
        sw2[2][widx][m] = wv[i];
    }

    float acc[12][4];
#pragma unroll
    for (int o = 0; o < 12; o++)
#pragma unroll
        for (int p = 0; p < 4; p++) acc[o][p] = 0.f;

    for (int cc = 0; cc < 16; cc += 4) {
        __syncthreads();
        for (int e = tid; e < 4 * 18 * 66; e += 256) {
            int ch = e / (18 * 66);
            int r = (e / 66) % 18;
            int cl = e % 66;
            int gh = h0 + r - 1, gw = w0 + cl - 1;
            float v = 0.f;
            if ((unsigned)gh < 1024u && (unsigned)gw < 1024u)
                v = x[(((size_t)(b * 16 + cc + ch)) << 20) + gh * 1024 + gw];
            sx[ch][r][cl] = v;
        }
        __syncthreads();
#pragma unroll
        for (int ch = 0; ch < 4; ch++) {
#pragma unroll
            for (int dy = 0; dy < 3; dy++) {
                float xr[6];
                float4 xa = *(const float4*)&sx[ch][ty + dy][tx * 4];
                xr[0] = xa.x;
                xr[1] = xa.y;
                xr[2] = xa.z;
                xr[3] = xa.w;
                xr[4] = sx[ch][ty + dy][tx * 4 + 4];
                xr[5] = sx[ch][ty + dy][tx * 4 + 5];
#pragma unroll
                for (int dx = 0; dx < 3; dx++) {
                    int widx = (cc + ch) * 9 + dy * 3 + dx;
                    float4 w0v = *(const float4*)&sw2[0][widx][0];
                    float4 w1v = *(const float4*)&sw2[1][widx][0];
                    float4 w2v = *(const float4*)&sw2[2][widx][0];
#pragma unroll
                    for (int p = 0; p < 4; p++) {
                        float xv = xr[p + dx];
                        acc[0][p] += w0v.x * xv;
                        acc[1][p] += w0v.y * xv;
                        acc[2][p] += w0v.z * xv;
                        acc[3][p] += w0v.w * xv;
                        acc[4][p] += w1v.x * xv;
                        acc[5][p] += w1v.y * xv;
                        acc[6][p] += w1v.z * xv;
                        acc[7][p] += w1v.w * xv;
                        acc[8][p] += w2v.x * xv;
                        acc[9][p] += w2v.y * xv;
                        acc[10][p] += w2v.z * xv;
                        acc[11][p] += w2v.w * xv;
                    }
                }
            }
        }
    }

    // batched transposed store: 4 maps (one tensor t) per stage -> 6 syncs total
    const int wloc = tid >> 2, q = tid & 3;
#pragma unroll
    for (int t = 0; t < 3; t++) {
        const float* bias = (t == 0) ? bq : (t == 1) ? bk : bv;
        __syncthreads();
#pragma unroll
        for (int m = 0; m < 4; m++) {
            float bb = bias[m];
#pragma unroll
            for (int p = 0; p < 4; p++) st4[m][ty][tx * 4 + p] = acc[t * 4 + m][p] + bb;
        }
        __syncthreads();
#pragma unroll
        for (int m = 0; m < 4; m++) {
            float4 v = make_float4(st4[m][q * 4 + 0][wloc], st4[m][q * 4 + 1][wloc],
                                   st4[m][q * 4 + 2][wloc], st4[m][q * 4 + 3][wloc]);
            *(float4*)&g_yt[t][b * 4 + m][tiled_off(w0 + wloc, h0 + q * 4)] = v;
        }
    }
}

// ---------------- pw linear (merged q,k,v; ring): q/k (+rope) -> tiled; v -> V^T tiled ----
__global__ __launch_bounds__(256, 2) void gemm_pw_t() {
    const int m0 = blockIdx.x * 128;  // w
    const int n0 = blockIdx.y * 128;  // f
    const int t = blockIdx.z >> 3;
    const int b4 = blockIdx.z & 7;
    const int am = b4 & 3;
    GEMM_PROLOG_RING;

    const float* A = &g_yt[t][b4][(size_t)(m0 >> 7) * TMB];
    const float* B = &g_wt[t][am][(size_t)(n0 >> 7) * TMB];
    ring_mainloop(A, B, 32, sh, mbF, mbE, acc, tid, lane, warpM, warpN);

    if (t < 2) {
        float* Out = g_qkm[t][b4];
#pragma unroll
        for (int mt = 0; mt < 2; mt++)
#pragma unroll
            for (int half = 0; half < 2; half++) {
                int w = m0 + warpM * 32 + mt * 16 + gid + half * 8;
                size_t rb = (size_t)(w >> 7) * TMB + (w & 127) * TSTR;
#pragma unroll
                for (int nt = 0; nt < 8; nt++) {
                    int f = n0 + warpN * 64 + nt * 8 + 2 * tig;
                    float v0 = acc[mt][nt][half * 2 + 0];
                    float v1 = acc[mt][nt][half * 2 + 1];
                    {
                        int j0 = (f >> 1) & 63;
                        float c = g_cos[w * 64 + j0], s = g_sin[w * 64 + j0];
                        float e = v0 * c - v1 * s, o = v1 * c + v0 * s;
                        v0 = e;
                        v1 = o;
                    }
                    *(float2*)&Out[rb + (size_t)(f >> 5) * TSLAB + (f & 31)] =
                        make_float2(v0, v1);
                }
            }
    } else {
        float* ts = sh;  // reuse mainloop buffers: 128 x 132 transpose stage
#pragma unroll
        for (int mt = 0; mt < 2; mt++)
#pragma unroll
            for (int half = 0; half < 2; half++) {
                int ml = warpM * 32 + mt * 16 + gid + half * 8;
#pragma unroll
                for (int nt = 0; nt < 8; nt++) {
                    int nl = warpN * 64 + nt * 8 + 2 * tig;
                    ts[ml * 132 + nl] = acc[mt][nt][half * 2 + 0];
                    ts[ml * 132 + nl + 1] = acc[mt][nt][half * 2 + 1];
                }
            }
        __syncthreads();
        float* Out = g_vt[b4];
        const int fl = tid >> 1, hf = tid & 1;
        int f = n0 + fl;
        size_t rb = (size_t)(f >> 7) * TMB + (f & 127) * TSTR;
#pragma unroll
        for (int i = 0; i < 64; i += 4) {
            int wl = hf * 64 + i;
            float4 v = make_float4(ts[(wl + 0) * 132 + fl], ts[(wl + 1) * 132 + fl],
                                   ts[(wl + 2) * 132 + fl], ts[(wl + 3) * 132 + fl]);
            int w = m0 + wl;
            *(float4*)&Out[rb + (size_t)(w >> 5) * TSLAB + (w & 31)] = v;
        }
    }
}

// ---------------- qk (r8 loop): S = qk^T/32 + prev + mask (S only) ----------------
__global__ __launch_bounds__(256, 2) void gemm_qk_t(const float* __restrict__ prev_qk,
                                                    const float* __restrict__ mask,
                                                    float* __restrict__ qk_out) {
    const int m0 = blockIdx.x * 128;
    const int n0 = blockIdx.y * 128;
    const int bh = blockIdx.z;
    const int b4 = bh >> 3, head = bh & 7;
    GEMM_PROLOG2;

    const float* A = &g_qkm[0][b4][(size_t)(m0 >> 7) * TMB + (size_t)(head * 4) * TSLAB];
    const float* B = &g_qkm[1][b4][(size_t)(n0 >> 7) * TMB + (size_t)(head * 4) * TSLAB];
    bulk_mainloop(A, B, 4, sh, mb0, acc, tid, lane, warpM, warpN);

    const float* prevb = prev_qk + ((size_t)bh << 20);
    float* outb = qk_out + ((size_t)bh << 20);
#pragma unroll
    for (int mt = 0; mt < 2; mt++)
#pragma unroll
        for (int half = 0; half < 2; half++) {
            int mi = m0 + warpM * 32 + mt * 16 + gid + half * 8;
#pragma unroll
            for (int nt = 0; nt < 8; nt++) {
                int n = n0 + warpN * 64 + nt * 8 + 2 * tig;
                float2 pv = *(const float2*)&prevb[(size_t)mi * 1024 + n];
                float2 mk = *(const float2*)&mask[(size_t)mi * 1024 + n];
                float2 r;
                r.x = acc[mt][nt][half * 2 + 0] * 0.03125f + pv.x + mk.x;
                r.y = acc[mt][nt][half * 2 + 1] * 0.03125f + pv.y + mk.y;
                *(float2*)&outb[(size_t)mi * 1024 + n] = r;
            }
        }
}

// ---------------- pv: A_att = (exp(S) @ V) / rowsum; exp + rowsum computed in-kernel -----
__global__ __launch_bounds__(256, 2) void gemm_pv_t(const float* __restrict__ S) {
    const int m0 = blockIdx.x * 128;
    const int bh = blockIdx.y;
    const int b4 = bh >> 3, head = bh & 7;
    extern __shared__ __align__(16) float sh[];
    __shared__ __align__(8) unsigned long long s_mb[2];
    __shared__ float sred[128];
    const int tid = threadIdx.x;
    const int lane = tid & 31, warp = tid >> 5, warpM = warp & 3, warpN = warp >> 2;
    const int gid = lane >> 2, tig = lane & 3;
    if (tid == 0) {
        MBARRIER_INIT(sptr(&s_mb[0]), 1);
        MBARRIER_INIT(sptr(&s_mb[1]), 1);
    }
    __syncthreads();
    const unsigned mb0 = sptr(&s_mb[0]);
    float acc[2][8][4] = {};

    float* Abuf = sh;                 // 2 x TSLAB: staged exp(S) m-major
    float* Bbuf = sh + 2 * TSLAB;     // 2 x TSLAB: V tiles
    const unsigned shuB = sptr(Bbuf);
    const float* Vb = &g_vt[b4][(size_t)head * TMB];

    if (tid == 0) {
        bulk_expect(mb0, TSLAB_B);
        bulk_cp(shuB, Vb, mb0);
        bulk_expect(mb0 + 8, TSLAB_B);
        bulk_cp(shuB + TSLAB_B, Vb + TSLAB, mb0 + 8);
    }

    const int row = tid >> 1, kh = (tid & 1) * 16;
    const float* Sr = S + ((size_t)bh << 20) + (size_t)(m0 + row) * 1024 + kh;
    float4 p0 = *(const float4*)&Sr[0];
    float4 p1 = *(const float4*)&Sr[4];
    float4 p2 = *(const float4*)&Sr[8];
    float4 p3 = *(const float4*)&Sr[12];
    float rsum = 0.f;
    int ph0 = 0, ph1 = 0;

    for (int it = 0; it < 32; it++) {
        const int s = it & 1;
        if (s == 0) {
            MBARRIER_WAIT_PARITY(mb0, ph0);
            ph0 ^= 1;
        } else {
            MBARRIER_WAIT_PARITY(mb0 + 8, ph1);
            ph1 ^= 1;
        }
        {
            float* dst = Abuf + s * TSLAB + row * TSTR + kh;
            float e0 = __expf(p0.x), e1 = __expf(p0.y), e2 = __expf(p0.z), e3 = __expf(p0.w);
            float e4 = __expf(p1.x), e5 = __expf(p1.y), e6 = __expf(p1.z), e7 = __expf(p1.w);
            float e8 = __expf(p2.x), e9 = __expf(p2.y), ea = __expf(p2.z), eb = __expf(p2.w);
            float ec = __expf(p3.x), ed = __expf(p3.y), ee = __expf(p3.z), ef = __expf(p3.w);
            *(float4*)&dst[0] = make_float4(e0, e1, e2, e3);
            *(float4*)&dst[4] = make_float4(e4, e5, e6, e7);
            *(float4*)&dst[8] = make_float4(e8, e9, ea, eb);
            *(float4*)&dst[12] = make_float4(ec, ed, ee, ef);
            rsum += ((e0 + e1) + (e2 + e3)) + ((e4 + e5) + (e6 + e7)) +
                    ((e8 + e9) + (ea + eb)) + ((ec + ed) + (ee + ef));
        }
        if (it + 1 < 32) {
            const float* Sn = Sr + (size_t)(it + 1) * 32;
            p0 = *(const float4*)&Sn[0];
            p1 = *(const float4*)&Sn[4];
            p2 = *(const float4*)&Sn[8];
            p3 = *(const float4*)&Sn[12];
        }
        __syncthreads();
        fc_mm(Abuf + s * TSLAB, Bbuf + s * TSLAB, 0, acc, lane, warpM, warpN);
        fc_mm(Abuf + s * TSLAB, Bbuf + s * TSLAB, 16, acc, lane, warpM, warpN);
        __syncthreads();
        if (tid == 0 && it + 2 < 32) {
            const unsigned mb = mb0 + s * 8;
            bulk_expect(mb, TSLAB_B);
            bulk_cp(shuB + s * TSLAB_B, Vb + (size_t)(it + 2) * TSLAB, mb);
        }
    }

    rsum += __shfl_xor_sync(0xffffffffu, rsum, 1);
    if ((tid & 1) == 0) sred[row] = 1.0f / rsum;
    __syncthreads();

    float* Ab = g_a[b4];
#pragma unroll
    for (int mt = 0; mt < 2; mt++)
#pragma unroll
        for (int half = 0; half < 2; half++) {
            int ml = warpM * 32 + mt * 16 + gid + half * 8;
            int mi = m0 + ml;
            float rv = sred[ml];
#pragma unroll
            for (int nt = 0; nt < 8; nt++) {
                int n = warpN * 64 + nt * 8 + 2 * tig;
                float2 r = make_float2(acc[mt][nt][half * 2 + 0] * rv,
                                       acc[mt][nt][half * 2 + 1] * rv);
                *(float2*)&Ab[(size_t)mi * 1024 + head * 128 + n] = r;
            }
        }
}

// ---------------- 4x4 depthwise channel mix -> tiled g_aot ----------------
__global__ __launch_bounds__(256) void dw_kernel(const float* __restrict__ dw) {
    int idx = blockIdx.x * 256 + threadIdx.x;
    int b = idx >> 18;
    size_t off = ((size_t)(idx & 262143)) << 2;
    int w = (int)(off >> 10), h = (int)(off & 1023);
    size_t toff = tiled_off(w, h);
    float4 a[4];
#pragma unroll
    for (int c = 0; c < 4; c++) a[c] = *(const float4*)&g_a[b * 4 + c][off];
#pragma unroll
    for (int o = 0; o < 4; o++) {
        float w0 = dw[o * 4 + 0], w1 = dw[o * 4 + 1], w2 = dw[o * 4 + 2], w3 = dw[o * 4 + 3];
        float4 r;
        r.x = w0 * a[0].x + w1 * a[1].x + w2 * a[2].x + w3 * a[3].x;
        r.y = w0 * a[0].y + w1 * a[1].y + w2 * a[2].y + w3 * a[3].y;
        r.z = w0 * a[0].z + w1 * a[1].z + w2 * a[2].z + w3 * a[3].z;
        r.w = w0 * a[0].w + w1 * a[1].w + w2 * a[2].w + w3 * a[3].w;
        *(float4*)&g_aot[b * 4 + o][toff] = r;
    }
}

// ---------------- wo_pw (r8 loop): Out[f][w] = W * Ao^T (plain out) ----------------
__global__ __launch_bounds__(256, 2) void gemm_wo_t() {
    const int m0 = blockIdx.x * 128;  // f
    const int n0 = blockIdx.y * 128;  // w
    const int b4 = blockIdx.z;
    const int am = b4 & 3;
    GEMM_PROLOG2;

    const float* A = &g_wt[3][am][(size_t)(m0 >> 7) * TMB];
    const float* B = &g_aot[b4][(size_t)(n0 >> 7) * TMB];
    bulk_mainloop(A, B, 32, sh, mb0, acc, tid, lane, warpM, warpN);

    float* Out = g_a2[b4];
#pragma unroll
    for (int mt = 0; mt < 2; mt++)
#pragma unroll
        for (int half = 0; half < 2; half++) {
            int mi = m0 + warpM * 32 + mt * 16 + gid + half * 8;
#pragma unroll
            for (int nt = 0; nt < 8; nt++) {
                int n = n0 + warpN * 64 + nt * 8 + 2 * tig;
                float2 r = make_float2(acc[mt][nt][half * 2 + 0], acc[mt][nt][half * 2 + 1]);
                *(float2*)&Out[(size_t)mi * 1024 + n] = r;
            }
        }
}

// ---------------- final conv 3x3 over concat(x[16], a2[4]) -> 16 channels ----------------
// weights repacked output-major in smem: sw2[widx][o] -> four float4 cover 16 outs
__global__ __launch_bounds__(256) void conv_out_kernel(const float* __restrict__ x,
                                                       const float* __restrict__ wo,
                                                       const float* __restrict__ bo,
                                                       float* __restrict__ out) {
    __shared__ __align__(16) float sx[4][18][68];
    __shared__ __align__(16) float sw2[180][16];
    const int b = blockIdx.x;
    const int h0 = blockIdx.y * 16;
    const int w0 = blockIdx.z * 64;
    const int tx = threadIdx.x, ty = threadIdx.y;
    const int tid = ty * 16 + tx;

    for (int i = tid; i < 2880; i += 256) {
        int o = i / 180, widx = i % 180;
        sw2[widx][o] = wo[i];
    }

    float acc[16][4];
#pragma unroll
    for (int o = 0; o < 16; o++)
#pragma unroll
        for (int p = 0; p < 4; p++) acc[o][p] = 0.f;

    for (int cc = 0; cc < 20; cc += 4) {
        __syncthreads();
        for (int e = tid; e < 4 * 18 * 66; e += 256) {
            int ch = e / (18 * 66);
            int r = (e / 66) % 18;
            int cl = e % 66;
            int gh = h0 + r - 1, gw = w0 + cl - 1;
            int c = cc + ch;
            float v = 0.f;
            if ((unsigned)gh < 1024u && (unsigned)gw < 1024u) {
                const float* src = (c < 16) ? (x + (((size_t)(b * 16 + c)) << 20))
                                            : g_a2[b * 4 + (c - 16)];
                v = src[gh * 1024 + gw];
            }
            sx[ch][r][cl] = v;
        }
        __syncthreads();
#pragma unroll
        for (int ch = 0; ch < 4; ch++) {
#pragma unroll
            for (int dy = 0; dy < 3; dy++) {
                float xr[6];
                float4 xa = *(const float4*)&sx[ch][ty + dy][tx * 4];
                xr[0] = xa.x;
                xr[1] = xa.y;
                xr[2] = xa.z;
                xr[3] = xa.w;
                xr[4] = sx[ch][ty + dy][tx * 4 + 4];
                xr[5] = sx[ch][ty + dy][tx * 4 + 5];
#pragma unroll
                for (int dx = 0; dx < 3; dx++) {
                    int widx = (cc + ch) * 9 + dy * 3 + dx;
                    float4 w0v = *(const float4*)&sw2[widx][0];
                    float4 w1v = *(const float4*)&sw2[widx][4];
                    float4 w2v = *(const float4*)&sw2[widx][8];
                    float4 w3v = *(const float4*)&sw2[widx][12];
#pragma unroll
                    for (int p = 0; p < 4; p++) {
                        float xv = xr[p + dx];
                        acc[0][p] += w0v.x * xv;
                        acc[1][p] += w0v.y * xv;
                        acc[2][p] += w0v.z * xv;
                        acc[3][p] += w0v.w * xv;
                        acc[4][p] += w1v.x * xv;
                        acc[5][p] += w1v.y * xv;
                        acc[6][p] += w1v.z * xv;
                        acc[7][p] += w1v.w * xv;
                        acc[8][p] += w2v.x * xv;
                        acc[9][p] += w2v.y * xv;
                        acc[10][p] += w2v.z * xv;
                        acc[11][p] += w2v.w * xv;
                        acc[12][p] += w3v.x * xv;
                        acc[13][p] += w3v.y * xv;
                        acc[14][p] += w3v.z * xv;
                        acc[15][p] += w3v.w * xv;
                    }
                }
            }
        }
    }

    int gh = h0 + ty, gw = w0 + tx * 4;
#pragma unroll
    for (int o = 0; o < 16; o++) {
        float bb = bo[o];
        float4 v = make_float4(acc[o][0] + bb, acc[o][1] + bb, acc[o][2] + bb, acc[o][3] + bb);
        *(float4*)&out[(((size_t)(b * 16 + o)) << 20) + gh * 1024 + gw] = v;
    }
}

// ---------------- launch ----------------
extern "C" void kernel_launch(void* const* d_in, const int* in_sizes, int n_in,
                              void* d_out, int out_size) {
    const float* x       = (const float*)d_in[0];
    const float* prev_qk = (const float*)d_in[1];
    const float* mask    = (const float*)d_in[2];
    const float* wq_conv = (const float*)d_in[3];
    const float* bq_conv = (const float*)d_in[4];
    const float* wq_pw   = (const float*)d_in[5];
    const float* wk_conv = (const float*)d_in[6];
    const float* bk_conv = (const float*)d_in[7];
    const float* wk_pw   = (const float*)d_in[8];
    const float* wv_conv = (const float*)d_in[9];
    const float* bv_conv = (const float*)d_in[10];
    const float* wv_pw   = (const float*)d_in[11];
    const float* wo_pw   = (const float*)d_in[12];
    const float* wo_dw   = (const float*)d_in[13];
    const float* wo_conv = (const float*)d_in[14];
    const float* bo_conv = (const float*)d_in[15];

    float* outp = (float*)d_out;                       // (2,16,1024,1024)
    float* qk_out = outp + (size_t)NB * NC * NF * NW;  // (2,4,8,1024,1024)

    const int GM_SM = 4 * TSLAB_B;   // 73728  (qk, pv, wo)
    const int PW_SM = 6 * TSLAB_B;   // 110592 (ring pw; 2 CTAs/SM)

    cudaFuncSetAttribute(gemm_pw_t, cudaFuncAttributeMaxDynamicSharedMemorySize, PW_SM);
    cudaFuncSetAttribute(gemm_qk_t, cudaFuncAttributeMaxDynamicSharedMemorySize, GM_SM);
    cudaFuncSetAttribute(gemm_pv_t, cudaFuncAttributeMaxDynamicSharedMemorySize, GM_SM);
    cudaFuncSetAttribute(gemm_wo_t, cudaFuncAttributeMaxDynamicSharedMemorySize, GM_SM);

    rope_init_kernel<<<256, 256>>>();
    repack4_kernel<<<dim3(8, 32, 16), 256>>>(wq_pw, wk_pw, wv_pw, wo_pw);
    conv_qkv_kernel<<<dim3(NB, 64, 16), dim3(16, 16)>>>(x, wq_conv, bq_conv,
                                                        wk_conv, bk_conv, wv_conv, bv_conv);
    gemm_pw_t<<<dim3(8, 8, 24), 256, PW_SM>>>();
    gemm_qk_t<<<dim3(8, 8, 64), 256, GM_SM>>>(prev_qk, mask, qk_out);
    gemm_pv_t<<<dim3(8, 64), 256, GM_SM>>>(qk_out);
    dw_kernel<<<2048, 256>>>(wo_dw);
    gemm_wo_t<<<dim3(8, 8, 8), 256, GM_SM>>>();
    conv_out_kernel<<<dim3(NB, 64, 16), dim3(16, 16)>>>(x, wo_conv, bo_conv, outp);
}

// round 17
// speedup vs baseline: 1.3842x; 1.0858x over previous
#include <cuda_runtime.h>
#include <math.h>

// Problem dims
#define NB 2
#define NC 16
#define NAM 4
#define NHEADS 8
#define NF 1024
#define NW 1024
#define NHD 128

// Tiled-slab layout: slab = 128 rows x 32 k, rows padded to 36 words -> 18432B contiguous
#define TSTR 36
#define TSLAB 4608
#define TSLAB_B 18432u
#define TMB 147456
#define TMAT 1179648

// ---------------- scratch (device globals; no runtime allocation) ----------------
__device__ float g_yt[3][8][TMAT];      // conv outputs tiled: rows=w, k=h
__device__ float g_qkm[2][8][TMAT];     // q,k tiled: rows=w, k=f
__device__ float g_vt[8][TMAT];         // V^T tiled: rows=f, k=w
__device__ float g_wt[4][4][TMAT];      // repacked weights [q,k,v,o][am]: rows=f, k=h
__device__ float g_aot[8][TMAT];        // after dw mix tiled: rows=w, k=h
__device__ float g_a[8][NW * NF];       // attention out plain [w][f]
__device__ float g_a2[8][NF * NW];      // after wo_pw plain [f][w]
__device__ float g_cos[NW * (NHD / 2)];
__device__ float g_sin[NW * (NHD / 2)];

// ---------------- helpers ----------------
__device__ __forceinline__ unsigned sptr(const void* p) {
    return (unsigned)__cvta_generic_to_shared(p);
}
__device__ __forceinline__ size_t tiled_off(int row, int k) {
    return (size_t)(row >> 7) * TMB + (size_t)(k >> 5) * TSLAB + (row & 127) * TSTR + (k & 31);
}

#define MBARRIER_INIT(addr, count) \
    asm volatile("mbarrier.init.shared.b64 [%0], %1;" ::"r"(addr), "r"(count) : "memory")

#define MBARRIER_WAIT_PARITY(addr, parity)                                              \
    do {                                                                                \
        unsigned _mb = (addr), _pa = (parity), _done;                                   \
        asm volatile(                                                                   \
            "{\n\t.reg .pred p;\n\t"                                                    \
            "mbarrier.try_wait.parity.acquire.cta.shared::cta.b64 p, [%1], %2;\n\t"     \
            "selp.b32 %0, 1, 0, p;\n\t}"                                                \
            : "=r"(_done) : "r"(_mb), "r"(_pa) : "memory");                             \
        if (!_done) {                                                                   \
            asm volatile(                                                               \
                "{\n\t.reg .pred P1;\n\t"                                               \
                "WL_%=:\n\t"                                                            \
                "mbarrier.try_wait.parity.acquire.cta.shared::cta.b64 P1, [%0], %1, 0x989680;\n\t" \
                "@P1 bra.uni WD_%=;\n\t"                                                \
                "bra.uni WL_%=;\n\t"                                                    \
                "WD_%=:\n\t}" ::"r"(_mb), "r"(_pa) : "memory");                         \
        }                                                                               \
    } while (0)

#define MBARRIER_ARRIVE(addr) \
    asm volatile("mbarrier.arrive.shared.b64 _, [%0];" ::"r"(addr) : "memory")

__device__ __forceinline__ void bulk_expect(unsigned mb, unsigned bytes) {
    asm volatile("mbarrier.arrive.expect_tx.shared.b64 _, [%0], %1;" ::"r"(mb), "r"(bytes)
                 : "memory");
}
__device__ __forceinline__ void bulk_cp(unsigned dst, const float* src, unsigned mb) {
    asm volatile(
        "cp.async.bulk.shared::cta.global.mbarrier::complete_tx::bytes [%0], [%1], %2, [%3];"
        ::"r"(dst), "l"(src), "r"(TSLAB_B), "r"(mb)
        : "memory");
}

__device__ __forceinline__ void ldsm_x4(unsigned r[4], const void* p) {
    asm volatile("ldmatrix.sync.aligned.m8n8.x4.shared.b16 {%0,%1,%2,%3}, [%4];"
                 : "=r"(r[0]), "=r"(r[1]), "=r"(r[2]), "=r"(r[3])
                 : "r"(sptr(p)));
}
__device__ __forceinline__ void mma_tf32(float* c, unsigned a0, unsigned a1, unsigned a2,
                                         unsigned a3, unsigned b0, unsigned b1) {
    asm volatile(
        "mma.sync.aligned.m16n8k8.row.col.f32.tf32.tf32.f32 "
        "{%0,%1,%2,%3}, {%4,%5,%6,%7}, {%8,%9}, {%0,%1,%2,%3};"
        : "+f"(c[0]), "+f"(c[1]), "+f"(c[2]), "+f"(c[3])
        : "r"(a0), "r"(a1), "r"(a2), "r"(a3), "r"(b0), "r"(b1));
}

// fragment compute over one 16-k window at word-offset ko; both operands m-major (TSTR)
__device__ __forceinline__ void fc_mm(const float* As, const float* Bs, int ko,
                                      float (&acc)[2][8][4], int lane, int warpM, int warpN) {
    const int la = lane & 15, ha = (lane >> 4) * 4;
    const int lb = lane & 7, hb = (lane >> 3) * 4;
    unsigned a[2][2][4];
#pragma unroll
    for (int mt = 0; mt < 2; mt++)
#pragma unroll
        for (int kk = 0; kk < 2; kk++)
            ldsm_x4(a[mt][kk], &As[(warpM * 32 + mt * 16 + la) * TSTR + ko + kk * 8 + ha]);
#pragma unroll
    for (int nh = 0; nh < 2; nh++) {
        unsigned b[4][4];
#pragma unroll
        for (int j = 0; j < 4; j++)
            ldsm_x4(b[j], &Bs[(warpN * 64 + nh * 32 + j * 8 + lb) * TSTR + ko + hb]);
#pragma unroll
        for (int kk = 0; kk < 2; kk++)
#pragma unroll
            for (int mt = 0; mt < 2; mt++)
#pragma unroll
                for (int j = 0; j < 4; j++)
                    mma_tf32(acc[mt][nh * 4 + j], a[mt][kk][0], a[mt][kk][1], a[mt][kk][2],
                             a[mt][kk][3], b[j][kk * 2], b[j][kk * 2 + 1]);
    }
}

// ---- r8-proven: bulk-copy double-buffered mainloop (barrier cadence) ----
__device__ __forceinline__ void bulk_mainloop(const float* A, const float* B, int NIT,
                                              float* sh, unsigned mb0, float (&acc)[2][8][4],
                                              int tid, int lane, int warpM, int warpN) {
    const unsigned shu = sptr(sh);
    if (tid == 0) {
        bulk_expect(mb0, 2 * TSLAB_B);
        bulk_cp(shu, A, mb0);
        bulk_cp(shu + 2 * TSLAB_B, B, mb0);
        bulk_expect(mb0 + 8, 2 * TSLAB_B);
        bulk_cp(shu + TSLAB_B, A + TSLAB, mb0 + 8);
        bulk_cp(shu + 3 * TSLAB_B, B + TSLAB, mb0 + 8);
    }
    int ph0 = 0, ph1 = 0;
    for (int it = 0; it < NIT; it++) {
        const int s = it & 1;
        if (s == 0) {
            MBARRIER_WAIT_PARITY(mb0, ph0);
            ph0 ^= 1;
        } else {
            MBARRIER_WAIT_PARITY(mb0 + 8, ph1);
            ph1 ^= 1;
        }
        const float* As = sh + s * TSLAB;
        const float* Bs = sh + 2 * TSLAB + s * TSLAB;
        fc_mm(As, Bs, 0, acc, lane, warpM, warpN);
        fc_mm(As, Bs, 16, acc, lane, warpM, warpN);
        __syncthreads();
        if (it + 2 < NIT && tid == 0) {
            const unsigned mb = mb0 + s * 8;
            bulk_expect(mb, 2 * TSLAB_B);
            bulk_cp(shu + s * TSLAB_B, A + (size_t)(it + 2) * TSLAB, mb);
            bulk_cp(shu + 2 * TSLAB_B + s * TSLAB_B, B + (size_t)(it + 2) * TSLAB, mb);
        }
    }
}

// ---- r10-proven (pw only): 3-buffer producer/consumer ring, no per-iter sync ----
__device__ __forceinline__ void ring_mainloop(const float* A, const float* B, int NIT,
                                              float* sh, unsigned mbF, unsigned mbE,
                                              float (&acc)[2][8][4], int tid, int lane,
                                              int warpM, int warpN) {
    const unsigned shu = sptr(sh);
    if (tid == 0) {
        int npre = NIT < 3 ? NIT : 3;
        for (int s = 0; s < npre; s++) {
            bulk_expect(mbF + s * 8, 2 * TSLAB_B);
            bulk_cp(shu + s * TSLAB_B, A + (size_t)s * TSLAB, mbF + s * 8);
            bulk_cp(shu + (3 + s) * TSLAB_B, B + (size_t)s * TSLAB, mbF + s * 8);
        }
    }
    for (int it = 0; it < NIT; it++) {
        const int j = it % 3;
        const int u = (it / 3) & 1;
        MBARRIER_WAIT_PARITY(mbF + j * 8, u);
        const float* As = sh + j * TSLAB;
        const float* Bs = sh + (3 + j) * TSLAB;
        fc_mm(As, Bs, 0, acc, lane, warpM, warpN);
        fc_mm(As, Bs, 16, acc, lane, warpM, warpN);
        if (lane == 0) MBARRIER_ARRIVE(mbE + j * 8);
        if (tid == 0 && it + 3 < NIT) {
            MBARRIER_WAIT_PARITY(mbE + j * 8, u);
            bulk_expect(mbF + j * 8, 2 * TSLAB_B);
            bulk_cp(shu + j * TSLAB_B, A + (size_t)(it + 3) * TSLAB, mbF + j * 8);
            bulk_cp(shu + (3 + j) * TSLAB_B, B + (size_t)(it + 3) * TSLAB, mbF + j * 8);
        }
    }
    __syncthreads();  // quiesce before epilogue / smem reuse
}

#define GEMM_PROLOG2                                                         \
    extern __shared__ __align__(16) float sh[];                              \
    __shared__ __align__(8) unsigned long long s_mb[2];                      \
    const int tid = threadIdx.x;                                             \
    const int lane = tid & 31, warp = tid >> 5, warpM = warp & 3,            \
              warpN = warp >> 2;                                             \
    const int gid = lane >> 2, tig = lane & 3;                               \
    if (tid == 0) {                                                          \
        MBARRIER_INIT(sptr(&s_mb[0]), 1);                                    \
        MBARRIER_INIT(sptr(&s_mb[1]), 1);                                    \
    }                                                                        \
    __syncthreads();                                                         \
    const unsigned mb0 = sptr(&s_mb[0]);                                     \
    float acc[2][8][4] = {};

#define GEMM_PROLOG_RING                                                     \
    extern __shared__ __align__(16) float sh[];                              \
    __shared__ __align__(8) unsigned long long s_mb[6];                      \
    const int tid = threadIdx.x;                                             \
    const int lane = tid & 31, warp = tid >> 5, warpM = warp & 3,            \
              warpN = warp >> 2;                                             \
    const int gid = lane >> 2, tig = lane & 3;                               \
    if (tid == 0) {                                                          \
        _Pragma("unroll") for (int i = 0; i < 3; i++) {                      \
            MBARRIER_INIT(sptr(&s_mb[i]), 1);                                \
            MBARRIER_INIT(sptr(&s_mb[3 + i]), 8);                            \
        }                                                                    \
    }                                                                        \
    __syncthreads();                                                         \
    const unsigned mbF = sptr(&s_mb[0]);                                     \
    const unsigned mbE = sptr(&s_mb[3]);                                     \
    float acc[2][8][4] = {};

// ---------------- merged weight repack: 4 tensors -> g_wt tiled ----------------
__global__ __launch_bounds__(256) void repack4_kernel(const float* __restrict__ s0,
                                                      const float* __restrict__ s1,
                                                      const float* __restrict__ s2,
                                                      const float* __restrict__ s3) {
    const int which = blockIdx.z >> 2, am = blockIdx.z & 3;
    const float* base = (which == 0) ? s0 : (which == 1) ? s1 : (which == 2) ? s2 : s3;
    const float* s = base + ((size_t)am << 20) + ((size_t)blockIdx.x * 128) * 1024 +
                     blockIdx.y * 32;
    float* d = &g_wt[which][am][(size_t)blockIdx.x * TMB + (size_t)blockIdx.y * TSLAB];
    const int warp = threadIdx.x >> 5, lane = threadIdx.x & 31;
#pragma unroll
    for (int i = 0; i < 16; i++) {
        int r = warp * 16 + i;
        d[r * TSTR + lane] = s[(size_t)r * 1024 + lane];
    }
}

// ---------------- RoPE table init: fp64 angle, fp32 trig; chip-filling grid ----------------
__global__ void rope_init_kernel() {
    int idx = blockIdx.x * blockDim.x + threadIdx.x;
    if (idx >= NW * 64) return;
    int w = idx >> 6, j = idx & 63;
    double inv = exp(-((double)(2 * j) / (double)NHD) * log(10000.0));
    float ang = (float)((double)w * inv);
    g_cos[idx] = cosf(ang);
    g_sin[idx] = sinf(ang);
}

// ---------------- conv 3x3 (16 -> 4) writing tiled-transposed Yt (rows=w, k=h) ------------
// weights repacked output-major in smem: sw2[t][widx][m] -> one float4 covers 4 maps
__global__ __launch_bounds__(256) void conv_qkv_kernel(
    const float* __restrict__ x,
    const float* __restrict__ wq, const float* __restrict__ bq,
    const float* __restrict__ wk, const float* __restrict__ bk,
    const float* __restrict__ wv, const float* __restrict__ bv) {
    __shared__ __align__(16) float sx[4][18][68];
    __shared__ __align__(16) float sw2[3][144][4];
    __shared__ __align__(16) float st4[4][16][68];
    const int b = blockIdx.x;
    const int h0 = blockIdx.y * 16;
    const int w0 = blockIdx.z * 64;
    const int tx = threadIdx.x, ty = threadIdx.y;
    const int tid = ty * 16 + tx;

    for (int i = tid; i < 576; i += 256) {
        int m = i / 144, widx = i % 144;
        sw2[0][widx][m] = wq[i];
        sw2[1][widx][m] = wk[i];
        sw2[2][widx][m] = wv[i];
    }

    float acc[12][4];
#pragma unroll
    for (int o = 0; o < 12; o++)
#pragma unroll
        for (int p = 0; p < 4; p++) acc[o][p] = 0.f;

    for (int cc = 0; cc < 16; cc += 4) {
        __syncthreads();
        for (int e = tid; e < 4 * 18 * 66; e += 256) {
            int ch = e / (18 * 66);
            int r = (e / 66) % 18;
            int cl = e % 66;
            int gh = h0 + r - 1, gw = w0 + cl - 1;
            float v = 0.f;
            if ((unsigned)gh < 1024u && (unsigned)gw < 1024u)
                v = x[(((size_t)(b * 16 + cc + ch)) << 20) + gh * 1024 + gw];
            sx[ch][r][cl] = v;
        }
        __syncthreads();
#pragma unroll
        for (int ch = 0; ch < 4; ch++) {
#pragma unroll
            for (int dy = 0; dy < 3; dy++) {
                float xr[6];
                float4 xa = *(const float4*)&sx[ch][ty + dy][tx * 4];
                xr[0] = xa.x;
                xr[1] = xa.y;
                xr[2] = xa.z;
                xr[3] = xa.w;
                xr[4] = sx[ch][ty + dy][tx * 4 + 4];
                xr[5] = sx[ch][ty + dy][tx * 4 + 5];
#pragma unroll
                for (int dx = 0; dx < 3; dx++) {
                    int widx = (cc + ch) * 9 + dy * 3 + dx;
                    float4 w0v = *(const float4*)&sw2[0][widx][0];
                    float4 w1v = *(const float4*)&sw2[1][widx][0];
                    float4 w2v = *(const float4*)&sw2[2][widx][0];
#pragma unroll
                    for (int p = 0; p < 4; p++) {
                        float xv = xr[p + dx];
                        acc[0][p] += w0v.x * xv;
                        acc[1][p] += w0v.y * xv;
                        acc[2][p] += w0v.z * xv;
                        acc[3][p] += w0v.w * xv;
                        acc[4][p] += w1v.x * xv;
                        acc[5][p] += w1v.y * xv;
                        acc[6][p] += w1v.z * xv;
                        acc[7][p] += w1v.w * xv;
                        acc[8][p] += w2v.x * xv;
                        acc[9][p] += w2v.y * xv;
                        acc[10][p] += w2v.z * xv;
                        acc[11][p] += w2v.w * xv;
                    }
                }
            }
        }
    }

    // batched transposed store: 4 maps (one tensor t) per stage -> 6 syncs total
    const int wloc = tid >> 2, q = tid & 3;
#pragma unroll
    for (int t = 0; t < 3; t++) {
        const float* bias = (t == 0) ? bq : (t == 1) ? bk : bv;
        __syncthreads();
#pragma unroll
        for (int m = 0; m < 4; m++) {
            float bb = bias[m];
#pragma unroll
            for (int p = 0; p < 4; p++) st4[m][ty][tx * 4 + p] = acc[t * 4 + m][p] + bb;
        }
        __syncthreads();
#pragma unroll
        for (int m = 0; m < 4; m++) {
            float4 v = make_float4(st4[m][q * 4 + 0][wloc], st4[m][q * 4 + 1][wloc],
                                   st4[m][q * 4 + 2][wloc], st4[m][q * 4 + 3][wloc]);
            *(float4*)&g_yt[t][b * 4 + m][tiled_off(w0 + wloc, h0 + q * 4)] = v;
        }
    }
}

// ---------------- pw linear (merged q,k,v; ring): q/k (+rope) -> tiled; v -> V^T tiled ----
__global__ __launch_bounds__(256, 2) void gemm_pw_t() {
    const int m0 = blockIdx.x * 128;  // w
    const int n0 = blockIdx.y * 128;  // f
    const int t = blockIdx.z >> 3;
    const int b4 = blockIdx.z & 7;
    const int am = b4 & 3;
    GEMM_PROLOG_RING;

    const float* A = &g_yt[t][b4][(size_t)(m0 >> 7) * TMB];
    const float* B = &g_wt[t][am][(size_t)(n0 >> 7) * TMB];
    ring_mainloop(A, B, 32, sh, mbF, mbE, acc, tid, lane, warpM, warpN);

    if (t < 2) {
        float* Out = g_qkm[t][b4];
#pragma unroll
        for (int mt = 0; mt < 2; mt++)
#pragma unroll
            for (int half = 0; half < 2; half++) {
                int w = m0 + warpM * 32 + mt * 16 + gid + half * 8;
                size_t rb = (size_t)(w >> 7) * TMB + (w & 127) * TSTR;
#pragma unroll
                for (int nt = 0; nt < 8; nt++) {
                    int f = n0 + warpN * 64 + nt * 8 + 2 * tig;
                    float v0 = acc[mt][nt][half * 2 + 0];
                    float v1 = acc[mt][nt][half * 2 + 1];
                    {
                        int j0 = (f >> 1) & 63;
                        float c = g_cos[w * 64 + j0], s = g_sin[w * 64 + j0];
                        float e = v0 * c - v1 * s, o = v1 * c + v0 * s;
                        v0 = e;
                        v1 = o;
                    }
                    *(float2*)&Out[rb + (size_t)(f >> 5) * TSLAB + (f & 31)] =
                        make_float2(v0, v1);
                }
            }
    } else {
        float* ts = sh;  // reuse mainloop buffers: 128 x 132 transpose stage
#pragma unroll
        for (int mt = 0; mt < 2; mt++)
#pragma unroll
            for (int half = 0; half < 2; half++) {
                int ml = warpM * 32 + mt * 16 + gid + half * 8;
#pragma unroll
                for (int nt = 0; nt < 8; nt++) {
                    int nl = warpN * 64 + nt * 8 + 2 * tig;
                    ts[ml * 132 + nl] = acc[mt][nt][half * 2 + 0];
                    ts[ml * 132 + nl + 1] = acc[mt][nt][half * 2 + 1];
                }
            }
        __syncthreads();
        float* Out = g_vt[b4];
        const int fl = tid >> 1, hf = tid & 1;
        int f = n0 + fl;
        size_t rb = (size_t)(f >> 7) * TMB + (f & 127) * TSTR;
#pragma unroll
        for (int i = 0; i < 64; i += 4) {
            int wl = hf * 64 + i;
            float4 v = make_float4(ts[(wl + 0) * 132 + fl], ts[(wl + 1) * 132 + fl],
                                   ts[(wl + 2) * 132 + fl], ts[(wl + 3) * 132 + fl]);
            int w = m0 + wl;
            *(float4*)&Out[rb + (size_t)(w >> 5) * TSLAB + (w & 31)] = v;
        }
    }
}

// ---------------- qk (r8 loop): S = qk^T/32 + prev + mask (S only) ----------------
__global__ __launch_bounds__(256, 2) void gemm_qk_t(const float* __restrict__ prev_qk,
                                                    const float* __restrict__ mask,
                                                    float* __restrict__ qk_out) {
    const int m0 = blockIdx.x * 128;
    const int n0 = blockIdx.y * 128;
    const int bh = blockIdx.z;
    const int b4 = bh >> 3, head = bh & 7;
    GEMM_PROLOG2;

    const float* A = &g_qkm[0][b4][(size_t)(m0 >> 7) * TMB + (size_t)(head * 4) * TSLAB];
    const float* B = &g_qkm[1][b4][(size_t)(n0 >> 7) * TMB + (size_t)(head * 4) * TSLAB];
    bulk_mainloop(A, B, 4, sh, mb0, acc, tid, lane, warpM, warpN);

    const float* prevb = prev_qk + ((size_t)bh << 20);
    float* outb = qk_out + ((size_t)bh << 20);
#pragma unroll
    for (int mt = 0; mt < 2; mt++)
#pragma unroll
        for (int half = 0; half < 2; half++) {
            int mi = m0 + warpM * 32 + mt * 16 + gid + half * 8;
#pragma unroll
            for (int nt = 0; nt < 8; nt++) {
                int n = n0 + warpN * 64 + nt * 8 + 2 * tig;
                float2 pv = *(const float2*)&prevb[(size_t)mi * 1024 + n];
                float2 mk = *(const float2*)&mask[(size_t)mi * 1024 + n];
                float2 r;
                r.x = acc[mt][nt][half * 2 + 0] * 0.03125f + pv.x + mk.x;
                r.y = acc[mt][nt][half * 2 + 1] * 0.03125f + pv.y + mk.y;
                *(float2*)&outb[(size_t)mi * 1024 + n] = r;
            }
        }
}

// ---------------- pv: A_att = (exp(S) @ V) / rowsum; exp + rowsum computed in-kernel -----
__global__ __launch_bounds__(256, 2) void gemm_pv_t(const float* __restrict__ S) {
    const int m0 = blockIdx.x * 128;
    const int bh = blockIdx.y;
    const int b4 = bh >> 3, head = bh & 7;
    extern __shared__ __align__(16) float sh[];
    __shared__ __align__(8) unsigned long long s_mb[2];
    __shared__ float sred[128];
    const int tid = threadIdx.x;
    const int lane = tid & 31, warp = tid >> 5, warpM = warp & 3, warpN = warp >> 2;
    const int gid = lane >> 2, tig = lane & 3;
    if (tid == 0) {
        MBARRIER_INIT(sptr(&s_mb[0]), 1);
        MBARRIER_INIT(sptr(&s_mb[1]), 1);
    }
    __syncthreads();
    const unsigned mb0 = sptr(&s_mb[0]);
    float acc[2][8][4] = {};

    float* Abuf = sh;                 // 2 x TSLAB: staged exp(S) m-major
    float* Bbuf = sh + 2 * TSLAB;     // 2 x TSLAB: V tiles
    const unsigned shuB = sptr(Bbuf);
    const float* Vb = &g_vt[b4][(size_t)head * TMB];

    if (tid == 0) {
        bulk_expect(mb0, TSLAB_B);
        bulk_cp(shuB, Vb, mb0);
        bulk_expect(mb0 + 8, TSLAB_B);
        bulk_cp(shuB + TSLAB_B, Vb + TSLAB, mb0 + 8);
    }

    const int row = tid >> 1, kh = (tid & 1) * 16;
    const float* Sr = S + ((size_t)bh << 20) + (size_t)(m0 + row) * 1024 + kh;
    float4 p0 = *(const float4*)&Sr[0];
    float4 p1 = *(const float4*)&Sr[4];
    float4 p2 = *(const float4*)&Sr[8];
    float4 p3 = *(const float4*)&Sr[12];
    float rsum = 0.f;
    int ph0 = 0, ph1 = 0;

    for (int it = 0; it < 32; it++) {
        const int s = it & 1;
        if (s == 0) {
            MBARRIER_WAIT_PARITY(mb0, ph0);
            ph0 ^= 1;
        } else {
            MBARRIER_WAIT_PARITY(mb0 + 8, ph1);
            ph1 ^= 1;
        }
        {
            float* dst = Abuf + s * TSLAB + row * TSTR + kh;
            float e0 = __expf(p0.x), e1 = __expf(p0.y), e2 = __expf(p0.z), e3 = __expf(p0.w);
            float e4 = __expf(p1.x), e5 = __expf(p1.y), e6 = __expf(p1.z), e7 = __expf(p1.w);
            float e8 = __expf(p2.x), e9 = __expf(p2.y), ea = __expf(p2.z), eb = __expf(p2.w);
            float ec = __expf(p3.x), ed = __expf(p3.y), ee = __expf(p3.z), ef = __expf(p3.w);
            *(float4*)&dst[0] = make_float4(e0, e1, e2, e3);
            *(float4*)&dst[4] = make_float4(e4, e5, e6, e7);
            *(float4*)&dst[8] = make_float4(e8, e9, ea, eb);
            *(float4*)&dst[12] = make_float4(ec, ed, ee, ef);
            rsum += ((e0 + e1) + (e2 + e3)) + ((e4 + e5) + (e6 + e7)) +
                    ((e8 + e9) + (ea + eb)) + ((ec + ed) + (ee + ef));
        }
        if (it + 1 < 32) {
            const float* Sn = Sr + (size_t)(it + 1) * 32;
            p0 = *(const float4*)&Sn[0];
            p1 = *(const float4*)&Sn[4];
            p2 = *(const float4*)&Sn[8];
            p3 = *(const float4*)&Sn[12];
        }
        __syncthreads();
        fc_mm(Abuf + s * TSLAB, Bbuf + s * TSLAB, 0, acc, lane, warpM, warpN);
        fc_mm(Abuf + s * TSLAB, Bbuf + s * TSLAB, 16, acc, lane, warpM, warpN);
        __syncthreads();
        if (tid == 0 && it + 2 < 32) {
            const unsigned mb = mb0 + s * 8;
            bulk_expect(mb, TSLAB_B);
            bulk_cp(shuB + s * TSLAB_B, Vb + (size_t)(it + 2) * TSLAB, mb);
        }
    }

    rsum += __shfl_xor_sync(0xffffffffu, rsum, 1);
    if ((tid & 1) == 0) sred[row] = 1.0f / rsum;
    __syncthreads();

    float* Ab = g_a[b4];
#pragma unroll
    for (int mt = 0; mt < 2; mt++)
#pragma unroll
        for (int half = 0; half < 2; half++) {
            int ml = warpM * 32 + mt * 16 + gid + half * 8;
            int mi = m0 + ml;
            float rv = sred[ml];
#pragma unroll
            for (int nt = 0; nt < 8; nt++) {
                int n = warpN * 64 + nt * 8 + 2 * tig;
                float2 r = make_float2(acc[mt][nt][half * 2 + 0] * rv,
                                       acc[mt][nt][half * 2 + 1] * rv);
                *(float2*)&Ab[(size_t)mi * 1024 + head * 128 + n] = r;
            }
        }
}

// ---------------- 4x4 depthwise channel mix -> tiled g_aot ----------------
__global__ __launch_bounds__(256) void dw_kernel(const float* __restrict__ dw) {
    int idx = blockIdx.x * 256 + threadIdx.x;
    int b = idx >> 18;
    size_t off = ((size_t)(idx & 262143)) << 2;
    int w = (int)(off >> 10), h = (int)(off & 1023);
    size_t toff = tiled_off(w, h);
    float4 a[4];
#pragma unroll
    for (int c = 0; c < 4; c++) a[c] = *(const float4*)&g_a[b * 4 + c][off];
#pragma unroll
    for (int o = 0; o < 4; o++) {
        float w0 = dw[o * 4 + 0], w1 = dw[o * 4 + 1], w2 = dw[o * 4 + 2], w3 = dw[o * 4 + 3];
        float4 r;
        r.x = w0 * a[0].x + w1 * a[1].x + w2 * a[2].x + w3 * a[3].x;
        r.y = w0 * a[0].y + w1 * a[1].y + w2 * a[2].y + w3 * a[3].y;
        r.z = w0 * a[0].z + w1 * a[1].z + w2 * a[2].z + w3 * a[3].z;
        r.w = w0 * a[0].w + w1 * a[1].w + w2 * a[2].w + w3 * a[3].w;
        *(float4*)&g_aot[b * 4 + o][toff] = r;
    }
}

// ---------------- wo_pw (r8 loop): Out[f][w] = W * Ao^T (plain out) ----------------
__global__ __launch_bounds__(256, 2) void gemm_wo_t() {
    const int m0 = blockIdx.x * 128;  // f
    const int n0 = blockIdx.y * 128;  // w
    const int b4 = blockIdx.z;
    const int am = b4 & 3;
    GEMM_PROLOG2;

    const float* A = &g_wt[3][am][(size_t)(m0 >> 7) * TMB];
    const float* B = &g_aot[b4][(size_t)(n0 >> 7) * TMB];
    bulk_mainloop(A, B, 32, sh, mb0, acc, tid, lane, warpM, warpN);

    float* Out = g_a2[b4];
#pragma unroll
    for (int mt = 0; mt < 2; mt++)
#pragma unroll
        for (int half = 0; half < 2; half++) {
            int mi = m0 + warpM * 32 + mt * 16 + gid + half * 8;
#pragma unroll
            for (int nt = 0; nt < 8; nt++) {
                int n = n0 + warpN * 64 + nt * 8 + 2 * tig;
                float2 r = make_float2(acc[mt][nt][half * 2 + 0], acc[mt][nt][half * 2 + 1]);
                *(float2*)&Out[(size_t)mi * 1024 + n] = r;
            }
        }
}

// ---------------- final conv 3x3 (tensor-core): out[16] = W[16x180] conv concat(x,a2) ----
// 27 accumulated m16n8k8 tf32 MMAs per pixel group: 3 channel-chunks x 9 taps.
// smem: swA [3][9][8 k][40 pad] (o-major inner), sx [8ch][18][68]
__global__ __launch_bounds__(256, 2) void conv_out_tc(const float* __restrict__ x,
                                                      const float* __restrict__ wo,
                                                      const float* __restrict__ bo,
                                                      float* __restrict__ out) {
    extern __shared__ __align__(16) float sh[];
    float* swA = sh;            // 3*9*320 = 8640 floats
    float* sx = sh + 8640;      // 8*18*68 = 9792 floats
    const int b = blockIdx.x;
    const int h0 = blockIdx.y * 16;
    const int w0 = blockIdx.z * 64;
    const int tid = threadIdx.x;
    const int lane = tid & 31, warp = tid >> 5;
    const int gid = lane >> 2, tig = lane & 3;

    // load weights: swA[chunk][tap][k][o], zero-pad channels 20..23
    for (int i = tid; i < 3456; i += 256) {
        int o = i & 15;
        int k = (i >> 4) & 7;
        int tap = (i >> 7) % 9;
        int ch = i / 1152;
        int c = ch * 8 + k;
        float v = (c < 20) ? wo[o * 180 + c * 9 + tap] : 0.f;
        swA[ch * 2880 + tap * 320 + k * 40 + o] = v;
    }

    float acc[16][4];
#pragma unroll
    for (int f = 0; f < 16; f++)
#pragma unroll
        for (int p = 0; p < 4; p++) acc[f][p] = 0.f;

    for (int cc = 0; cc < 3; cc++) {
        __syncthreads();
        for (int e = tid; e < 8 * 18 * 66; e += 256) {
            int ch = e / (18 * 66);
            int r = (e / 66) % 18;
            int cl = e % 66;
            int gh = h0 + r - 1, gw = w0 + cl - 1;
            int c = cc * 8 + ch;
            float v = 0.f;
            if (c < 20 && (unsigned)gh < 1024u && (unsigned)gw < 1024u) {
                const float* src = (c < 16) ? (x + (((size_t)(b * 16 + c)) << 20))
                                            : g_a2[b * 4 + (c - 16)];
                v = src[gh * 1024 + gw];
            }
            sx[ch * 1224 + r * 68 + cl] = v;
        }
        __syncthreads();
        const float* wA0 = swA + cc * 2880;
#pragma unroll
        for (int dy = 0; dy < 3; dy++)
#pragma unroll
            for (int dx = 0; dx < 3; dx++) {
                const float* wA = wA0 + (dy * 3 + dx) * 320;
                unsigned a0 = __float_as_uint(wA[tig * 40 + gid]);
                unsigned a1 = __float_as_uint(wA[tig * 40 + gid + 8]);
                unsigned a2 = __float_as_uint(wA[(tig + 4) * 40 + gid]);
                unsigned a3 = __float_as_uint(wA[(tig + 4) * 40 + gid + 8]);
#pragma unroll
                for (int f = 0; f < 16; f++) {
                    int r = 2 * warp + (f >> 3) + dy;
                    int col = (f & 7) * 8 + gid + dx;
                    unsigned b0 = __float_as_uint(sx[tig * 1224 + r * 68 + col]);
                    unsigned b1 = __float_as_uint(sx[(tig + 4) * 1224 + r * 68 + col]);
                    mma_tf32(acc[f], a0, a1, a2, a3, b0, b1);
                }
            }
    }

    const float b0v = bo[gid], b1v = bo[gid + 8];
    float* outb = out + (((size_t)(b * 16)) << 20);
#pragma unroll
    for (int f = 0; f < 16; f++) {
        int gh = h0 + 2 * warp + (f >> 3);
        int gw = w0 + (f & 7) * 8 + 2 * tig;
        *(float2*)&outb[(((size_t)gid) << 20) + gh * 1024 + gw] =
            make_float2(acc[f][0] + b0v, acc[f][1] + b0v);
        *(float2*)&outb[(((size_t)(gid + 8)) << 20) + gh * 1024 + gw] =
            make_float2(acc[f][2] + b1v, acc[f][3] + b1v);
    }
}

// ---------------- launch ----------------
extern "C" void kernel_launch(void* const* d_in, const int* in_sizes, int n_in,
                              void* d_out, int out_size) {
    const float* x       = (const float*)d_in[0];
    const float* prev_qk = (const float*)d_in[1];
    const float* mask    = (const float*)d_in[2];
    const float* wq_conv = (const float*)d_in[3];
    const float* bq_conv = (const float*)d_in[4];
    const float* wq_pw   = (const float*)d_in[5];
    const float* wk_conv = (const float*)d_in[6];
    const float* bk_conv = (const float*)d_in[7];
    const float* wk_pw   = (const float*)d_in[8];
    const float* wv_conv = (const float*)d_in[9];
    const float* bv_conv = (const float*)d_in[10];
    const float* wv_pw   = (const float*)d_in[11];
    const float* wo_pw   = (const float*)d_in[12];
    const float* wo_dw   = (const float*)d_in[13];
    const float* wo_conv = (const float*)d_in[14];
    const float* bo_conv = (const float*)d_in[15];

    float* outp = (float*)d_out;                       // (2,16,1024,1024)
    float* qk_out = outp + (size_t)NB * NC * NF * NW;  // (2,4,8,1024,1024)

    const int GM_SM = 4 * TSLAB_B;    // 73728  (qk, pv, wo)
    const int PW_SM = 6 * TSLAB_B;    // 110592 (ring pw; 2 CTAs/SM)
    const int CO_SM = 18432 * 4;      // 73728  (conv_out_tc: swA 8640 + sx 9792 floats)

    cudaFuncSetAttribute(gemm_pw_t, cudaFuncAttributeMaxDynamicSharedMemorySize, PW_SM);
    cudaFuncSetAttribute(gemm_qk_t, cudaFuncAttributeMaxDynamicSharedMemorySize, GM_SM);
    cudaFuncSetAttribute(gemm_pv_t, cudaFuncAttributeMaxDynamicSharedMemorySize, GM_SM);
    cudaFuncSetAttribute(gemm_wo_t, cudaFuncAttributeMaxDynamicSharedMemorySize, GM_SM);
    cudaFuncSetAttribute(conv_out_tc, cudaFuncAttributeMaxDynamicSharedMemorySize, CO_SM);

    rope_init_kernel<<<256, 256>>>();
    repack4_kernel<<<dim3(8, 32, 16), 256>>>(wq_pw, wk_pw, wv_pw, wo_pw);
    conv_qkv_kernel<<<dim3(NB, 64, 16), dim3(16, 16)>>>(x, wq_conv, bq_conv,
                                                        wk_conv, bk_conv, wv_conv, bv_conv);
    gemm_pw_t<<<dim3(8, 8, 24), 256, PW_SM>>>();
    gemm_qk_t<<<dim3(8, 8, 64), 256, GM_SM>>>(prev_qk, mask, qk_out);
    gemm_pv_t<<<dim3(8, 64), 256, GM_SM>>>(qk_out);
    dw_kernel<<<2048, 256>>>(wo_dw);
    gemm_wo_t<<<dim3(8, 8, 8), 256, GM_SM>>>();
    conv_out_tc<<<dim3(NB, 64, 16), 256, CO_SM>>>(x, wo_conv, bo_conv, outp);
}